// round 1
// baseline (speedup 1.0000x reference)
#include <cuda_runtime.h>
#include <math.h>

#define BATCH 512
#define NNODE 200
#define INC   200
#define HIDC  256
#define NVARS 2

// Scratch (allocation-free rule: __device__ globals)
__device__ float d_mask[NNODE * NNODE];
__device__ float d_support[BATCH * NNODE * HIDC];
__device__ float d_h1[BATCH * NNODE * HIDC];
__device__ float d_h2[BATCH * NNODE * HIDC];

// ---------------------------------------------------------------------------
// mask = (raw + raw^T) * 0.5 + I
// ---------------------------------------------------------------------------
__global__ void mask_kernel(const float* __restrict__ raw) {
    int i = blockIdx.x * blockDim.x + threadIdx.x;
    if (i < NNODE * NNODE) {
        int r = i / NNODE, c = i % NNODE;
        float v = 0.5f * (raw[r * NNODE + c] + raw[c * NNODE + r]);
        if (r == c) v += 1.0f;
        d_mask[i] = v;
    }
}

// ---------------------------------------------------------------------------
// C[M,N] = A[M,K] @ B[K,N]; M % 64 == 0, N % 64 == 0, K arbitrary.
// 64x64x16 tile, 256 threads, 4x4 microtile per thread.
// ---------------------------------------------------------------------------
__global__ __launch_bounds__(256) void gemm_feat(
    const float* __restrict__ A, const float* __restrict__ Bm,
    float* __restrict__ C, int M, int K, int N)
{
    const int BM = 64, BN = 64, BK = 16;
    __shared__ float As[BK][BM];
    __shared__ float Bs[BK][BN];

    int tid = threadIdx.x;
    int m0 = blockIdx.y * BM, n0 = blockIdx.x * BN;
    int tr = tid / 16, tc = tid % 16;

    float acc[4][4] = {};

    for (int k0 = 0; k0 < K; k0 += BK) {
        #pragma unroll
        for (int it = 0; it < (BM * BK) / 256; it++) {
            int i = tid + it * 256;
            int m = i / BK, k = i % BK;
            float v = (k0 + k < K) ? A[(size_t)(m0 + m) * K + k0 + k] : 0.0f;
            As[k][m] = v;
        }
        #pragma unroll
        for (int it = 0; it < (BK * BN) / 256; it++) {
            int i = tid + it * 256;
            int k = i / BN, n = i % BN;
            float v = (k0 + k < K) ? Bm[(size_t)(k0 + k) * N + n0 + n] : 0.0f;
            Bs[k][n] = v;
        }
        __syncthreads();

        #pragma unroll
        for (int k = 0; k < BK; k++) {
            float4 a4 = *reinterpret_cast<const float4*>(&As[k][tr * 4]);
            float4 b4 = *reinterpret_cast<const float4*>(&Bs[k][tc * 4]);
            float a[4] = {a4.x, a4.y, a4.z, a4.w};
            float b[4] = {b4.x, b4.y, b4.z, b4.w};
            #pragma unroll
            for (int i = 0; i < 4; i++)
                #pragma unroll
                for (int j = 0; j < 4; j++)
                    acc[i][j] += a[i] * b[j];
        }
        __syncthreads();
    }

    #pragma unroll
    for (int i = 0; i < 4; i++)
        #pragma unroll
        for (int j = 0; j < 4; j++)
            C[(size_t)(m0 + tr * 4 + i) * N + n0 + tc * 4 + j] = acc[i][j];
}

// ---------------------------------------------------------------------------
// Per-batch: Hout[b] = (sigmoid(adj[b]) * mask) @ S[b]
// M=K=200, N=256. A computed on the fly in the loader.
// grid: (N/64, ceil(200/64)=4, BATCH)
// ---------------------------------------------------------------------------
__global__ __launch_bounds__(256) void gemm_adj(
    const float* __restrict__ adj, const float* __restrict__ S,
    float* __restrict__ Hout)
{
    const int BM = 64, BN = 64, BK = 16;
    const int M = NNODE, K = NNODE, N = HIDC;

    int b = blockIdx.z;
    const float* A  = adj + (size_t)b * M * K;
    const float* Bm = S   + (size_t)b * K * N;
    float*       C  = Hout + (size_t)b * M * N;

    __shared__ float As[BK][BM];
    __shared__ float Bs[BK][BN];

    int tid = threadIdx.x;
    int m0 = blockIdx.y * BM, n0 = blockIdx.x * BN;
    int tr = tid / 16, tc = tid % 16;

    float acc[4][4] = {};

    for (int k0 = 0; k0 < K; k0 += BK) {
        #pragma unroll
        for (int it = 0; it < (BM * BK) / 256; it++) {
            int i = tid + it * 256;
            int m = i / BK, k = i % BK;
            int gm = m0 + m, gk = k0 + k;
            float v = 0.0f;
            if (gm < M && gk < K) {
                float x = A[gm * K + gk];
                float sg = 1.0f / (1.0f + __expf(-x));
                v = sg * d_mask[gm * K + gk];
            }
            As[k][m] = v;
        }
        #pragma unroll
        for (int it = 0; it < (BK * BN) / 256; it++) {
            int i = tid + it * 256;
            int k = i / BN, n = i % BN;
            int gk = k0 + k;
            Bs[k][n] = (gk < K) ? Bm[gk * N + n0 + n] : 0.0f;
        }
        __syncthreads();

        #pragma unroll
        for (int k = 0; k < BK; k++) {
            float4 a4 = *reinterpret_cast<const float4*>(&As[k][tr * 4]);
            float4 b4 = *reinterpret_cast<const float4*>(&Bs[k][tc * 4]);
            float a[4] = {a4.x, a4.y, a4.z, a4.w};
            float b[4] = {b4.x, b4.y, b4.z, b4.w};
            #pragma unroll
            for (int i = 0; i < 4; i++)
                #pragma unroll
                for (int j = 0; j < 4; j++)
                    acc[i][j] += a[i] * b[j];
        }
        __syncthreads();
    }

    #pragma unroll
    for (int i = 0; i < 4; i++) {
        int gm = m0 + tr * 4 + i;
        if (gm < M) {
            #pragma unroll
            for (int j = 0; j < 4; j++)
                C[(size_t)gm * N + n0 + tc * 4 + j] = acc[i][j];
        }
    }
}

// ---------------------------------------------------------------------------
// out[b, v] = (mean_n H[b,n,:]) @ pw + pb
// ---------------------------------------------------------------------------
__global__ __launch_bounds__(256) void readout_kernel(
    const float* __restrict__ H, const float* __restrict__ pw,
    const float* __restrict__ pb, float* __restrict__ out)
{
    int b = blockIdx.x;
    int c = threadIdx.x;  // 0..255
    const float* Hb = H + (size_t)b * NNODE * HIDC;

    float s = 0.0f;
    for (int n = 0; n < NNODE; n++) s += Hb[n * HIDC + c];
    s *= (1.0f / NNODE);

    __shared__ float r0[256], r1[256];
    r0[c] = s * pw[c * NVARS + 0];
    r1[c] = s * pw[c * NVARS + 1];
    __syncthreads();
    for (int off = 128; off > 0; off >>= 1) {
        if (c < off) { r0[c] += r0[c + off]; r1[c] += r1[c + off]; }
        __syncthreads();
    }
    if (c == 0) {
        out[b * NVARS + 0] = r0[0] + pb[0];
        out[b * NVARS + 1] = r1[0] + pb[1];
    }
}

// ---------------------------------------------------------------------------
extern "C" void kernel_launch(void* const* d_in, const int* in_sizes, int n_in,
                              void* d_out, int out_size)
{
    const float* adj      = (const float*)d_in[0];
    const float* features = (const float*)d_in[1];
    const float* raw      = (const float*)d_in[2];
    const float* W0       = (const float*)d_in[3];
    const float* W1       = (const float*)d_in[4];
    const float* W2       = (const float*)d_in[5];
    const float* pw       = (const float*)d_in[6];
    const float* pb       = (const float*)d_in[7];
    float* out = (float*)d_out;

    float *support, *h1, *h2;
    cudaGetSymbolAddress((void**)&support, d_support);
    cudaGetSymbolAddress((void**)&h1, d_h1);
    cudaGetSymbolAddress((void**)&h2, d_h2);

    const int M = BATCH * NNODE;  // 102400

    mask_kernel<<<(NNODE * NNODE + 255) / 256, 256>>>(raw);

    dim3 gridF(HIDC / 64, M / 64);          // (4, 1600)
    dim3 gridA(HIDC / 64, (NNODE + 63) / 64, BATCH);  // (4, 4, 512)

    // Layer 0: support = features @ W0 ; h1 = Adj @ support
    gemm_feat<<<gridF, 256>>>(features, W0, support, M, INC, HIDC);
    gemm_adj<<<gridA, 256>>>(adj, support, h1);

    // Layer 1: support = h1 @ W1 ; h2 = Adj @ support
    gemm_feat<<<gridF, 256>>>(h1, W1, support, M, HIDC, HIDC);
    gemm_adj<<<gridA, 256>>>(adj, support, h2);

    // Layer 2: support = h2 @ W2 ; h1 = Adj @ support
    gemm_feat<<<gridF, 256>>>(h2, W2, support, M, HIDC, HIDC);
    gemm_adj<<<gridA, 256>>>(adj, support, h1);

    // Readout
    readout_kernel<<<BATCH, 256>>>(h1, pw, pb, out);
}

// round 3
// speedup vs baseline: 3.2990x; 3.2990x over previous
#include <cuda_runtime.h>
#include <cuda_fp16.h>
#include <cstdint>
#include <math.h>

#define BATCH 512
#define NNODE 200
#define INC   200
#define HIDC  256
#define NVARS 2

// ---------------- scratch --------------------------------------------------
__device__ float d_mask[NNODE * NNODE];
__device__ float d_S [(size_t)BATCH * NNODE * HIDC];
__device__ float d_h1[(size_t)BATCH * NNODE * HIDC];
__device__ float d_h2[(size_t)BATCH * NNODE * HIDC];

// ---------------- smem stage layout (bytes) --------------------------------
// A: 128 rows x 16 halfs, row stride 48B (24 halfs) -> conflict-free lds.b32
// B: 16 k-rows x 128 n, row 256B, 16B-chunk swizzle c ^= (k&7) -> ldmatrix ok
#define ST_AHI 0
#define ST_ALO 6144
#define ST_BHI 12288
#define ST_BLO 16384
#define STAGE  20480

// ---------------- asm helpers ----------------------------------------------
__device__ __forceinline__ uint32_t cvta_s(const void* p) {
    uint32_t a;
    asm("{ .reg .u64 t; cvta.to.shared.u64 t, %1; cvt.u32.u64 %0, t; }" : "=r"(a) : "l"(p));
    return a;
}
__device__ __forceinline__ void sts128(uint32_t a, const uint32_t* x) {
    asm volatile("st.shared.v4.b32 [%0], {%1,%2,%3,%4};"
                 :: "r"(a), "r"(x[0]), "r"(x[1]), "r"(x[2]), "r"(x[3]));
}
__device__ __forceinline__ uint32_t lds32(uint32_t a) {
    uint32_t v; asm volatile("ld.shared.b32 %0, [%1];" : "=r"(v) : "r"(a)); return v;
}
__device__ __forceinline__ void ldmx4t(uint32_t a, uint32_t* r) {
    asm volatile("ldmatrix.sync.aligned.m8n8.x4.trans.shared.b16 {%0,%1,%2,%3}, [%4];"
                 : "=r"(r[0]), "=r"(r[1]), "=r"(r[2]), "=r"(r[3]) : "r"(a));
}
__device__ __forceinline__ void mma16816(float* c, const uint32_t* a, const uint32_t* b) {
    asm volatile(
        "mma.sync.aligned.m16n8k16.row.col.f32.f16.f16.f32 "
        "{%0,%1,%2,%3}, {%4,%5,%6,%7}, {%8,%9}, {%0,%1,%2,%3};"
        : "+f"(c[0]), "+f"(c[1]), "+f"(c[2]), "+f"(c[3])
        : "r"(a[0]), "r"(a[1]), "r"(a[2]), "r"(a[3]), "r"(b[0]), "r"(b[1]));
}

// fp32 -> (hi, lo) fp16 split, 8 values -> 4+4 packed u32
__device__ __forceinline__ void cvt8(const float* v, uint32_t* h, uint32_t* l) {
#pragma unroll
    for (int i = 0; i < 4; i++) {
        __half h0 = __float2half_rn(v[2*i]);
        __half h1 = __float2half_rn(v[2*i+1]);
        float r0 = v[2*i]   - __half2float(h0);
        float r1 = v[2*i+1] - __half2float(h1);
        __half l0 = __float2half_rn(r0);
        __half l1 = __float2half_rn(r1);
        h[i] = (uint32_t)__half_as_ushort(h0) | ((uint32_t)__half_as_ushort(h1) << 16);
        l[i] = (uint32_t)__half_as_ushort(l0) | ((uint32_t)__half_as_ushort(l1) << 16);
    }
}

// store one chunk's A (8 vals at row ar, k-octet akq) + B (8 vals at k bk, chunk bc)
__device__ __forceinline__ void store_stage(uint32_t stage, int ar, int akq, int bk, int bc,
                                            const float* aval, const float* bval) {
    uint32_t h[4], l[4];
    cvt8(aval, h, l);
    uint32_t aoff = (uint32_t)(ar * 48 + akq * 2);
    sts128(stage + ST_AHI + aoff, h);
    sts128(stage + ST_ALO + aoff, l);
    cvt8(bval, h, l);
    uint32_t boff = (uint32_t)(bk * 256 + ((bc ^ (bk & 7)) << 4));
    sts128(stage + ST_BHI + boff, h);
    sts128(stage + ST_BLO + boff, l);
}

// one k16 stage of MMA: 2 Mfrags x 8 Nfrags x 3 split products
__device__ __forceinline__ void mma_stage(uint32_t sb, int warp_m, int warp_n, int lane,
                                          float acc[2][8][4]) {
    int g = lane >> 2, t = lane & 3;
    uint32_t bhi[8][2], blo[8][2];
    int krow = ((lane & 8) ? 8 : 0) + (lane & 7);
    int csel = (lane & 16) ? 1 : 0;
#pragma unroll
    for (int jj = 0; jj < 4; jj++) {
        int cn = (warp_n >> 3) + jj * 2 + csel;
        uint32_t off = (uint32_t)(krow * 256 + ((cn ^ (krow & 7)) << 4));
        uint32_t r[4];
        ldmx4t(sb + ST_BHI + off, r);
        bhi[jj*2][0] = r[0]; bhi[jj*2][1] = r[1];
        bhi[jj*2+1][0] = r[2]; bhi[jj*2+1][1] = r[3];
        ldmx4t(sb + ST_BLO + off, r);
        blo[jj*2][0] = r[0]; blo[jj*2][1] = r[1];
        blo[jj*2+1][0] = r[2]; blo[jj*2+1][1] = r[3];
    }
#pragma unroll
    for (int i = 0; i < 2; i++) {
        uint32_t a0 = (uint32_t)((warp_m + i * 16 + g) * 48 + t * 4);
        uint32_t ahi[4], alo[4];
        ahi[0] = lds32(sb + ST_AHI + a0);
        ahi[1] = lds32(sb + ST_AHI + a0 + 8 * 48);
        ahi[2] = lds32(sb + ST_AHI + a0 + 16);
        ahi[3] = lds32(sb + ST_AHI + a0 + 8 * 48 + 16);
        alo[0] = lds32(sb + ST_ALO + a0);
        alo[1] = lds32(sb + ST_ALO + a0 + 8 * 48);
        alo[2] = lds32(sb + ST_ALO + a0 + 16);
        alo[3] = lds32(sb + ST_ALO + a0 + 8 * 48 + 16);
#pragma unroll
        for (int j = 0; j < 8; j++) {
            mma16816(acc[i][j], ahi, bhi[j]);
            mma16816(acc[i][j], ahi, blo[j]);
            mma16816(acc[i][j], alo, bhi[j]);
        }
    }
}

__device__ __forceinline__ void epilogue(float* __restrict__ C, int m0, int n0,
                                         int warp_m, int warp_n, int lane, int Mvalid,
                                         float acc[2][8][4]) {
    int g = lane >> 2, t = lane & 3;
#pragma unroll
    for (int i = 0; i < 2; i++) {
#pragma unroll
        for (int j = 0; j < 8; j++) {
            int row = m0 + warp_m + i * 16 + g;
            int col = n0 + warp_n + j * 8 + 2 * t;
            if (row < Mvalid)
                *(float2*)&C[(size_t)row * HIDC + col] = make_float2(acc[i][j][0], acc[i][j][1]);
            if (row + 8 < Mvalid)
                *(float2*)&C[(size_t)(row + 8) * HIDC + col] = make_float2(acc[i][j][2], acc[i][j][3]);
        }
    }
}

// ---------------------------------------------------------------------------
// feat GEMM: C[M,256] = A[M,K] @ B[K,256]; M multiple of 128
// ---------------------------------------------------------------------------
__global__ __launch_bounds__(256) void tc_feat(
    const float* __restrict__ A, const float* __restrict__ B,
    float* __restrict__ C, int K)
{
    __shared__ __align__(16) char smem[2 * STAGE];
    uint32_t sb0 = cvta_s(smem);
    int tid = threadIdx.x, lane = tid & 31, wid = tid >> 5;
    int warp_m = (wid >> 1) * 32, warp_n = (wid & 1) * 64;
    int m0 = blockIdx.y * 128, n0 = blockIdx.x * 128;
    int nch = (K + 15) >> 4;

    float acc[2][8][4];
#pragma unroll
    for (int i = 0; i < 2; i++)
#pragma unroll
        for (int j = 0; j < 8; j++)
#pragma unroll
            for (int q = 0; q < 4; q++) acc[i][j][q] = 0.0f;

    const int ar = tid >> 1, akq = (tid & 1) * 8;
    const int bk = tid >> 4, bc = tid & 15;

    float aval[8], bval[8];

    // --- load chunk 0 ---
    {
        const float* ap = A + (size_t)(m0 + ar) * K + akq;
        if (akq + 7 < K) {
            float4 v0 = *(const float4*)ap, v1 = *((const float4*)ap + 1);
            aval[0]=v0.x; aval[1]=v0.y; aval[2]=v0.z; aval[3]=v0.w;
            aval[4]=v1.x; aval[5]=v1.y; aval[6]=v1.z; aval[7]=v1.w;
        } else {
#pragma unroll
            for (int i = 0; i < 8; i++) aval[i] = (akq + i < K) ? ap[i] : 0.0f;
        }
        const float* bp = B + (size_t)bk * HIDC + n0 + bc * 8;
        if (bk < K) {
            float4 v0 = *(const float4*)bp, v1 = *((const float4*)bp + 1);
            bval[0]=v0.x; bval[1]=v0.y; bval[2]=v0.z; bval[3]=v0.w;
            bval[4]=v1.x; bval[5]=v1.y; bval[6]=v1.z; bval[7]=v1.w;
        } else {
#pragma unroll
            for (int i = 0; i < 8; i++) bval[i] = 0.0f;
        }
    }
    store_stage(sb0, ar, akq, bk, bc, aval, bval);
    __syncthreads();

    for (int ch = 0; ch < nch; ch++) {
        if (ch + 1 < nch) {
            int kc = (ch + 1) * 16;
            const float* ap = A + (size_t)(m0 + ar) * K + kc + akq;
            if (kc + akq + 7 < K) {
                float4 v0 = *(const float4*)ap, v1 = *((const float4*)ap + 1);
                aval[0]=v0.x; aval[1]=v0.y; aval[2]=v0.z; aval[3]=v0.w;
                aval[4]=v1.x; aval[5]=v1.y; aval[6]=v1.z; aval[7]=v1.w;
            } else {
#pragma unroll
                for (int i = 0; i < 8; i++) aval[i] = (kc + akq + i < K) ? ap[i] : 0.0f;
            }
            const float* bp = B + (size_t)(kc + bk) * HIDC + n0 + bc * 8;
            if (kc + bk < K) {
                float4 v0 = *(const float4*)bp, v1 = *((const float4*)bp + 1);
                bval[0]=v0.x; bval[1]=v0.y; bval[2]=v0.z; bval[3]=v0.w;
                bval[4]=v1.x; bval[5]=v1.y; bval[6]=v1.z; bval[7]=v1.w;
            } else {
#pragma unroll
                for (int i = 0; i < 8; i++) bval[i] = 0.0f;
            }
        }
        mma_stage(sb0 + (uint32_t)(ch & 1) * STAGE, warp_m, warp_n, lane, acc);
        if (ch + 1 < nch)
            store_stage(sb0 + (uint32_t)((ch + 1) & 1) * STAGE, ar, akq, bk, bc, aval, bval);
        __syncthreads();
    }

    epilogue(C, m0, n0, warp_m, warp_n, lane, 1 << 30, acc);
}

// ---------------------------------------------------------------------------
// adj GEMM (per batch z): H[200,256] = (sigmoid(adj_z)*mask)[200,200] @ S_z[200,256]
// ---------------------------------------------------------------------------
__global__ __launch_bounds__(256) void tc_adj(
    const float* __restrict__ adj, const float* __restrict__ S,
    float* __restrict__ H)
{
    __shared__ __align__(16) char smem[2 * STAGE];
    uint32_t sb0 = cvta_s(smem);
    int tid = threadIdx.x, lane = tid & 31, wid = tid >> 5;
    int warp_m = (wid >> 1) * 32, warp_n = (wid & 1) * 64;
    int m0 = blockIdx.y * 128, n0 = blockIdx.x * 128;
    int z = blockIdx.z;
    const float* Az = adj + (size_t)z * NNODE * NNODE;
    const float* Sz = S + (size_t)z * NNODE * HIDC;
    float* Hz = H + (size_t)z * NNODE * HIDC;
    const int K = NNODE;
    const int nch = (K + 15) >> 4;   // 13

    float acc[2][8][4];
#pragma unroll
    for (int i = 0; i < 2; i++)
#pragma unroll
        for (int j = 0; j < 8; j++)
#pragma unroll
            for (int q = 0; q < 4; q++) acc[i][j][q] = 0.0f;

    const int ar = tid >> 1, akq = (tid & 1) * 8;
    const int bk = tid >> 4, bc = tid & 15;
    const int gm = m0 + ar;

    float aval[8], bval[8];

    // chunk loader (A fused with sigmoid*mask)
    auto loadA = [&](int kc) {
        if (gm < NNODE) {
            const float* xp = Az + (size_t)gm * NNODE + kc + akq;
            const float* mp = d_mask + gm * NNODE + kc + akq;
            if (kc + akq + 7 < NNODE) {
                float4 x0 = *(const float4*)xp, x1 = *((const float4*)xp + 1);
                float4 k0 = *(const float4*)mp, k1 = *((const float4*)mp + 1);
                float xs[8] = {x0.x,x0.y,x0.z,x0.w,x1.x,x1.y,x1.z,x1.w};
                float ms[8] = {k0.x,k0.y,k0.z,k0.w,k1.x,k1.y,k1.z,k1.w};
#pragma unroll
                for (int i = 0; i < 8; i++)
                    aval[i] = ms[i] / (1.0f + __expf(-xs[i]));
            } else {
#pragma unroll
                for (int i = 0; i < 8; i++) {
                    int kk = kc + akq + i;
                    aval[i] = (kk < NNODE) ? mp[i] / (1.0f + __expf(-xp[i])) : 0.0f;
                }
            }
        } else {
#pragma unroll
            for (int i = 0; i < 8; i++) aval[i] = 0.0f;
        }
    };
    auto loadB = [&](int kc) {
        const float* bp = Sz + (size_t)(kc + bk) * HIDC + n0 + bc * 8;
        if (kc + bk < NNODE) {
            float4 v0 = *(const float4*)bp, v1 = *((const float4*)bp + 1);
            bval[0]=v0.x; bval[1]=v0.y; bval[2]=v0.z; bval[3]=v0.w;
            bval[4]=v1.x; bval[5]=v1.y; bval[6]=v1.z; bval[7]=v1.w;
        } else {
#pragma unroll
            for (int i = 0; i < 8; i++) bval[i] = 0.0f;
        }
    };

    loadA(0); loadB(0);
    store_stage(sb0, ar, akq, bk, bc, aval, bval);
    __syncthreads();

    for (int ch = 0; ch < nch; ch++) {
        if (ch + 1 < nch) { loadA((ch + 1) * 16); loadB((ch + 1) * 16); }
        mma_stage(sb0 + (uint32_t)(ch & 1) * STAGE, warp_m, warp_n, lane, acc);
        if (ch + 1 < nch)
            store_stage(sb0 + (uint32_t)((ch + 1) & 1) * STAGE, ar, akq, bk, bc, aval, bval);
        __syncthreads();
    }

    epilogue(Hz, m0, n0, warp_m, warp_n, lane, NNODE, acc);
}

// ---------------------------------------------------------------------------
__global__ void mask_kernel(const float* __restrict__ raw) {
    int i = blockIdx.x * blockDim.x + threadIdx.x;
    if (i < NNODE * NNODE) {
        int r = i / NNODE, c = i % NNODE;
        float v = 0.5f * (raw[r * NNODE + c] + raw[c * NNODE + r]);
        if (r == c) v += 1.0f;
        d_mask[i] = v;
    }
}

__global__ __launch_bounds__(256) void readout_kernel(
    const float* __restrict__ H, const float* __restrict__ pw,
    const float* __restrict__ pb, float* __restrict__ out)
{
    int b = blockIdx.x;
    int c = threadIdx.x;
    const float* Hb = H + (size_t)b * NNODE * HIDC;

    float s = 0.0f;
    for (int n = 0; n < NNODE; n++) s += Hb[n * HIDC + c];
    s *= (1.0f / NNODE);

    __shared__ float r0[256], r1[256];
    r0[c] = s * pw[c * NVARS + 0];
    r1[c] = s * pw[c * NVARS + 1];
    __syncthreads();
    for (int off = 128; off > 0; off >>= 1) {
        if (c < off) { r0[c] += r0[c + off]; r1[c] += r1[c + off]; }
        __syncthreads();
    }
    if (c == 0) {
        out[b * NVARS + 0] = r0[0] + pb[0];
        out[b * NVARS + 1] = r1[0] + pb[1];
    }
}

// ---------------------------------------------------------------------------
extern "C" void kernel_launch(void* const* d_in, const int* in_sizes, int n_in,
                              void* d_out, int out_size)
{
    const float* adj      = (const float*)d_in[0];
    const float* features = (const float*)d_in[1];
    const float* raw      = (const float*)d_in[2];
    const float* W0       = (const float*)d_in[3];
    const float* W1       = (const float*)d_in[4];
    const float* W2       = (const float*)d_in[5];
    const float* pw       = (const float*)d_in[6];
    const float* pb       = (const float*)d_in[7];
    float* out = (float*)d_out;

    float *S, *h1, *h2;
    cudaGetSymbolAddress((void**)&S, d_S);
    cudaGetSymbolAddress((void**)&h1, d_h1);
    cudaGetSymbolAddress((void**)&h2, d_h2);

    mask_kernel<<<(NNODE * NNODE + 255) / 256, 256>>>(raw);

    dim3 gF(2, (BATCH * NNODE) / 128);   // (2, 800)
    dim3 gA(2, 2, BATCH);                // (ntile, mtile, batch)

    tc_feat<<<gF, 256>>>(features, W0, S, INC);
    tc_adj <<<gA, 256>>>(adj, S, h1);

    tc_feat<<<gF, 256>>>(h1, W1, S, HIDC);
    tc_adj <<<gA, 256>>>(adj, S, h2);

    tc_feat<<<gF, 256>>>(h2, W2, S, HIDC);
    tc_adj <<<gA, 256>>>(adj, S, h1);

    readout_kernel<<<BATCH, 256>>>(h1, pw, pb, out);
}

// round 4
// speedup vs baseline: 3.7764x; 1.1447x over previous
#include <cuda_runtime.h>
#include <cuda_fp16.h>
#include <cstdint>
#include <math.h>

#define BATCH 512
#define NNODE 200
#define INC   200
#define HIDC  256
#define NVARS 2

// ---------------- scratch (fp16 hi/lo pairs) -------------------------------
__device__ float  d_mask[NNODE * NNODE];
__device__ __half d_Amh[(size_t)BATCH * NNODE * NNODE];   // sigmoid(adj)*mask hi
__device__ __half d_Aml[(size_t)BATCH * NNODE * NNODE];   // lo
__device__ __half d_Fh [(size_t)BATCH * NNODE * INC];     // features hi
__device__ __half d_Fl [(size_t)BATCH * NNODE * INC];
__device__ __half d_W0h[INC * HIDC],  d_W0l[INC * HIDC];
__device__ __half d_W1h[HIDC * HIDC], d_W1l[HIDC * HIDC];
__device__ __half d_W2h[HIDC * HIDC], d_W2l[HIDC * HIDC];
__device__ __half d_Sh [(size_t)BATCH * NNODE * HIDC], d_Sl [(size_t)BATCH * NNODE * HIDC];
__device__ __half d_H1h[(size_t)BATCH * NNODE * HIDC], d_H1l[(size_t)BATCH * NNODE * HIDC];
__device__ __half d_H2h[(size_t)BATCH * NNODE * HIDC], d_H2l[(size_t)BATCH * NNODE * HIDC];

// ---------------- smem stage layout (bytes) --------------------------------
// A: 128 rows x 16 halfs, row stride 48B  -> conflict-free ldmatrix
// B: 16 k-rows x 128 n halfs, row 256B, 16B-chunk swizzle c ^= (k&7)
#define ST_AHI 0
#define ST_ALO 6144
#define ST_BHI 12288
#define ST_BLO 16384
#define STAGE  20480

// ---------------- asm helpers ----------------------------------------------
__device__ __forceinline__ uint32_t cvta_s(const void* p) {
    uint32_t a;
    asm("{ .reg .u64 t; cvta.to.shared.u64 t, %1; cvt.u32.u64 %0, t; }" : "=r"(a) : "l"(p));
    return a;
}
__device__ __forceinline__ void sts128(uint32_t a, uint4 v) {
    asm volatile("st.shared.v4.b32 [%0], {%1,%2,%3,%4};"
                 :: "r"(a), "r"(v.x), "r"(v.y), "r"(v.z), "r"(v.w));
}
__device__ __forceinline__ void ldmx4(uint32_t a, uint32_t* r) {
    asm volatile("ldmatrix.sync.aligned.m8n8.x4.shared.b16 {%0,%1,%2,%3}, [%4];"
                 : "=r"(r[0]), "=r"(r[1]), "=r"(r[2]), "=r"(r[3]) : "r"(a));
}
__device__ __forceinline__ void ldmx4t(uint32_t a, uint32_t* r) {
    asm volatile("ldmatrix.sync.aligned.m8n8.x4.trans.shared.b16 {%0,%1,%2,%3}, [%4];"
                 : "=r"(r[0]), "=r"(r[1]), "=r"(r[2]), "=r"(r[3]) : "r"(a));
}
__device__ __forceinline__ void mma16816(float* c, const uint32_t* a, const uint32_t* b) {
    asm volatile(
        "mma.sync.aligned.m16n8k16.row.col.f32.f16.f16.f32 "
        "{%0,%1,%2,%3}, {%4,%5,%6,%7}, {%8,%9}, {%0,%1,%2,%3};"
        : "+f"(c[0]), "+f"(c[1]), "+f"(c[2]), "+f"(c[3])
        : "r"(a[0]), "r"(a[1]), "r"(a[2]), "r"(a[3]), "r"(b[0]), "r"(b[1]));
}

// fp32 pair -> packed hi/lo halves
__device__ __forceinline__ void split2(float a, float b, uint32_t& hi, uint32_t& lo) {
    __half ha = __float2half_rn(a), hb = __float2half_rn(b);
    __half la = __float2half_rn(a - __half2float(ha));
    __half lb = __float2half_rn(b - __half2float(hb));
    hi = (uint32_t)__half_as_ushort(ha) | ((uint32_t)__half_as_ushort(hb) << 16);
    lo = (uint32_t)__half_as_ushort(la) | ((uint32_t)__half_as_ushort(lb) << 16);
}

__device__ __forceinline__ void store_stage(uint32_t st, int ar, int asub, int bkr, int bch,
                                            uint4 avh, uint4 avl, uint4 bvh, uint4 bvl) {
    uint32_t ao = (uint32_t)(ar * 48 + asub * 16);
    sts128(st + ST_AHI + ao, avh);
    sts128(st + ST_ALO + ao, avl);
    uint32_t bo = (uint32_t)(bkr * 256 + ((bch ^ (bkr & 7)) << 4));
    sts128(st + ST_BHI + bo, bvh);
    sts128(st + ST_BLO + bo, bvl);
}

// one k16 stage: A via ldmatrix.x4, B via ldmatrix.x4.trans, 48 MMAs
__device__ __forceinline__ void mma_stage(uint32_t sb, int warp_m, int warp_n, int lane,
                                          float acc[2][8][4]) {
    uint32_t bhi[8][2], blo[8][2];
    int krow = lane & 15;
    int csel = (lane >> 4) & 1;
#pragma unroll
    for (int jj = 0; jj < 4; jj++) {
        int cn = (warp_n >> 3) + jj * 2 + csel;
        uint32_t off = (uint32_t)(krow * 256 + ((cn ^ (krow & 7)) << 4));
        uint32_t r[4];
        ldmx4t(sb + ST_BHI + off, r);
        bhi[jj*2][0] = r[0]; bhi[jj*2][1] = r[1];
        bhi[jj*2+1][0] = r[2]; bhi[jj*2+1][1] = r[3];
        ldmx4t(sb + ST_BLO + off, r);
        blo[jj*2][0] = r[0]; blo[jj*2][1] = r[1];
        blo[jj*2+1][0] = r[2]; blo[jj*2+1][1] = r[3];
    }
#pragma unroll
    for (int i = 0; i < 2; i++) {
        uint32_t ao = (uint32_t)((warp_m + i * 16 + (lane & 15)) * 48 + ((lane & 16) ? 16 : 0));
        uint32_t ahi[4], alo[4];
        ldmx4(sb + ST_AHI + ao, ahi);
        ldmx4(sb + ST_ALO + ao, alo);
#pragma unroll
        for (int j = 0; j < 8; j++) {
            mma16816(acc[i][j], ahi, bhi[j]);
            mma16816(acc[i][j], ahi, blo[j]);
            mma16816(acc[i][j], alo, bhi[j]);
        }
    }
}

__device__ __forceinline__ void epilogue_hl(__half* __restrict__ Ch, __half* __restrict__ Cl,
                                            int m0, int n0, int warp_m, int warp_n, int lane,
                                            int Mvalid, float acc[2][8][4]) {
    int g = lane >> 2, t = lane & 3;
#pragma unroll
    for (int i = 0; i < 2; i++) {
#pragma unroll
        for (int j = 0; j < 8; j++) {
            int row = m0 + warp_m + i * 16 + g;
            int col = n0 + warp_n + j * 8 + 2 * t;
            if (row < Mvalid) {
                uint32_t h, l;
                split2(acc[i][j][0], acc[i][j][1], h, l);
                *(uint32_t*)&Ch[(size_t)row * HIDC + col] = h;
                *(uint32_t*)&Cl[(size_t)row * HIDC + col] = l;
            }
            if (row + 8 < Mvalid) {
                uint32_t h, l;
                split2(acc[i][j][2], acc[i][j][3], h, l);
                *(uint32_t*)&Ch[(size_t)(row + 8) * HIDC + col] = h;
                *(uint32_t*)&Cl[(size_t)(row + 8) * HIDC + col] = l;
            }
        }
    }
}

// ---------------------------------------------------------------------------
// feat GEMM: C[M,256] = A[M,K] @ B[K,256]; all operands fp16 hi/lo pairs.
// ---------------------------------------------------------------------------
__global__ __launch_bounds__(256, 2) void tc_feat(
    const __half* __restrict__ Ah, const __half* __restrict__ Al,
    const __half* __restrict__ Bh, const __half* __restrict__ Bl,
    __half* __restrict__ Ch, __half* __restrict__ Cl, int K)
{
    __shared__ __align__(16) char smem[2 * STAGE];
    uint32_t sb0 = cvta_s(smem);
    int tid = threadIdx.x, lane = tid & 31, wid = tid >> 5;
    int warp_m = (wid >> 1) * 32, warp_n = (wid & 1) * 64;
    int m0 = blockIdx.y * 128, n0 = blockIdx.x * 128;
    int nch = (K + 15) >> 4;

    float acc[2][8][4];
#pragma unroll
    for (int i = 0; i < 2; i++)
#pragma unroll
        for (int j = 0; j < 8; j++)
#pragma unroll
            for (int q = 0; q < 4; q++) acc[i][j][q] = 0.0f;

    const int ar = tid >> 1, asub = tid & 1;
    const int bkr = tid >> 4, bch = tid & 15;

    uint4 avh, avl, bvh, bvl;
    const uint4 z4 = make_uint4(0, 0, 0, 0);

    auto loadA = [&](int kc) {
        bool p = (kc + asub * 8) < K;
        size_t off = (size_t)(m0 + ar) * K + kc + asub * 8;
        avh = p ? *(const uint4*)(Ah + off) : z4;
        avl = p ? *(const uint4*)(Al + off) : z4;
    };
    auto loadB = [&](int kc) {
        bool p = (kc + bkr) < K;
        size_t off = (size_t)(kc + bkr) * HIDC + n0 + bch * 8;
        bvh = p ? *(const uint4*)(Bh + off) : z4;
        bvl = p ? *(const uint4*)(Bl + off) : z4;
    };

    loadA(0); loadB(0);
    store_stage(sb0, ar, asub, bkr, bch, avh, avl, bvh, bvl);
    __syncthreads();

    for (int ch = 0; ch < nch; ch++) {
        if (ch + 1 < nch) { loadA((ch + 1) << 4); loadB((ch + 1) << 4); }
        mma_stage(sb0 + (uint32_t)(ch & 1) * STAGE, warp_m, warp_n, lane, acc);
        if (ch + 1 < nch)
            store_stage(sb0 + (uint32_t)((ch + 1) & 1) * STAGE, ar, asub, bkr, bch, avh, avl, bvh, bvl);
        __syncthreads();
    }

    epilogue_hl(Ch, Cl, m0, n0, warp_m, warp_n, lane, 1 << 30, acc);
}

// ---------------------------------------------------------------------------
// adj GEMM (per batch z): H[200,256] = Amask_z[200,200] @ S_z[200,256]
// ---------------------------------------------------------------------------
__global__ __launch_bounds__(256, 2) void tc_adj(
    const __half* __restrict__ Amh, const __half* __restrict__ Aml,
    const __half* __restrict__ Sh,  const __half* __restrict__ Sl,
    __half* __restrict__ Hh, __half* __restrict__ Hl)
{
    __shared__ __align__(16) char smem[2 * STAGE];
    uint32_t sb0 = cvta_s(smem);
    int tid = threadIdx.x, lane = tid & 31, wid = tid >> 5;
    int warp_m = (wid >> 1) * 32, warp_n = (wid & 1) * 64;
    int m0 = blockIdx.y * 128, n0 = blockIdx.x * 128;
    int z = blockIdx.z;
    const __half* Azh = Amh + (size_t)z * NNODE * NNODE;
    const __half* Azl = Aml + (size_t)z * NNODE * NNODE;
    const __half* Bzh = Sh + (size_t)z * NNODE * HIDC;
    const __half* Bzl = Sl + (size_t)z * NNODE * HIDC;
    __half* Czh = Hh + (size_t)z * NNODE * HIDC;
    __half* Czl = Hl + (size_t)z * NNODE * HIDC;
    const int K = NNODE, nch = 13;

    float acc[2][8][4];
#pragma unroll
    for (int i = 0; i < 2; i++)
#pragma unroll
        for (int j = 0; j < 8; j++)
#pragma unroll
            for (int q = 0; q < 4; q++) acc[i][j][q] = 0.0f;

    const int ar = tid >> 1, asub = tid & 1;
    const int bkr = tid >> 4, bch = tid & 15;
    const int gm = m0 + ar;

    uint4 avh, avl, bvh, bvl;
    const uint4 z4 = make_uint4(0, 0, 0, 0);

    auto loadA = [&](int kc) {
        bool p = (gm < NNODE) && ((kc + asub * 8) < K);
        size_t off = (size_t)gm * K + kc + asub * 8;
        avh = p ? *(const uint4*)(Azh + off) : z4;
        avl = p ? *(const uint4*)(Azl + off) : z4;
    };
    auto loadB = [&](int kc) {
        bool p = (kc + bkr) < K;
        size_t off = (size_t)(kc + bkr) * HIDC + n0 + bch * 8;
        bvh = p ? *(const uint4*)(Bzh + off) : z4;
        bvl = p ? *(const uint4*)(Bzl + off) : z4;
    };

    loadA(0); loadB(0);
    store_stage(sb0, ar, asub, bkr, bch, avh, avl, bvh, bvl);
    __syncthreads();

    for (int ch = 0; ch < nch; ch++) {
        if (ch + 1 < nch) { loadA((ch + 1) << 4); loadB((ch + 1) << 4); }
        mma_stage(sb0 + (uint32_t)(ch & 1) * STAGE, warp_m, warp_n, lane, acc);
        if (ch + 1 < nch)
            store_stage(sb0 + (uint32_t)((ch + 1) & 1) * STAGE, ar, asub, bkr, bch, avh, avl, bvh, bvl);
        __syncthreads();
    }

    epilogue_hl(Czh, Czl, m0, n0, warp_m, warp_n, lane, NNODE, acc);
}

// ---------------------------------------------------------------------------
// prep kernels
// ---------------------------------------------------------------------------
__global__ void mask_kernel(const float* __restrict__ raw) {
    int i = blockIdx.x * blockDim.x + threadIdx.x;
    if (i < NNODE * NNODE) {
        int r = i / NNODE, c = i % NNODE;
        float v = 0.5f * (raw[r * NNODE + c] + raw[c * NNODE + r]);
        if (r == c) v += 1.0f;
        d_mask[i] = v;
    }
}

__device__ __forceinline__ void split4_store(const float* v, __half* Hd, __half* Ld, size_t i4) {
    uint32_t h0, l0, h1, l1;
    split2(v[0], v[1], h0, l0);
    split2(v[2], v[3], h1, l1);
    ((uint2*)Hd)[i4] = make_uint2(h0, h1);
    ((uint2*)Ld)[i4] = make_uint2(l0, l1);
}

__global__ void amask_split_kernel(const float* __restrict__ adj) {
    size_t i4 = (size_t)blockIdx.x * blockDim.x + threadIdx.x;
    if (i4 >= (size_t)BATCH * NNODE * NNODE / 4) return;
    size_t base = i4 * 4;
    int rem = (int)(base % (NNODE * NNODE));
    float4 x = *(const float4*)(adj + base);
    float4 m = *(const float4*)(d_mask + rem);
    float v[4];
    v[0] = m.x / (1.0f + __expf(-x.x));
    v[1] = m.y / (1.0f + __expf(-x.y));
    v[2] = m.z / (1.0f + __expf(-x.z));
    v[3] = m.w / (1.0f + __expf(-x.w));
    split4_store(v, d_Amh, d_Aml, i4);
}

__global__ void feat_split_kernel(const float* __restrict__ f) {
    size_t i4 = (size_t)blockIdx.x * blockDim.x + threadIdx.x;
    if (i4 >= (size_t)BATCH * NNODE * INC / 4) return;
    float4 x = *(const float4*)(f + i4 * 4);
    float v[4] = {x.x, x.y, x.z, x.w};
    split4_store(v, d_Fh, d_Fl, i4);
}

__global__ void w_split_kernel(const float* __restrict__ w, __half* __restrict__ Hd,
                               __half* __restrict__ Ld, int total4) {
    int i4 = blockIdx.x * blockDim.x + threadIdx.x;
    if (i4 >= total4) return;
    float4 x = *(const float4*)(w + (size_t)i4 * 4);
    float v[4] = {x.x, x.y, x.z, x.w};
    split4_store(v, Hd, Ld, i4);
}

// ---------------------------------------------------------------------------
__global__ __launch_bounds__(256) void readout_kernel(
    const __half* __restrict__ Hh, const __half* __restrict__ Hl,
    const float* __restrict__ pw, const float* __restrict__ pb,
    float* __restrict__ out)
{
    int b = blockIdx.x;
    int c = threadIdx.x;
    const __half* Hbh = Hh + (size_t)b * NNODE * HIDC;
    const __half* Hbl = Hl + (size_t)b * NNODE * HIDC;

    float s = 0.0f;
    for (int n = 0; n < NNODE; n++)
        s += __half2float(Hbh[n * HIDC + c]) + __half2float(Hbl[n * HIDC + c]);
    s *= (1.0f / NNODE);

    __shared__ float r0[256], r1[256];
    r0[c] = s * pw[c * NVARS + 0];
    r1[c] = s * pw[c * NVARS + 1];
    __syncthreads();
    for (int off = 128; off > 0; off >>= 1) {
        if (c < off) { r0[c] += r0[c + off]; r1[c] += r1[c + off]; }
        __syncthreads();
    }
    if (c == 0) {
        out[b * NVARS + 0] = r0[0] + pb[0];
        out[b * NVARS + 1] = r1[0] + pb[1];
    }
}

// ---------------------------------------------------------------------------
extern "C" void kernel_launch(void* const* d_in, const int* in_sizes, int n_in,
                              void* d_out, int out_size)
{
    const float* adj      = (const float*)d_in[0];
    const float* features = (const float*)d_in[1];
    const float* raw      = (const float*)d_in[2];
    const float* W0       = (const float*)d_in[3];
    const float* W1       = (const float*)d_in[4];
    const float* W2       = (const float*)d_in[5];
    const float* pw       = (const float*)d_in[6];
    const float* pb       = (const float*)d_in[7];
    float* out = (float*)d_out;

    __half *Amh, *Aml, *Fh, *Fl, *W0h, *W0l, *W1h, *W1l, *W2h, *W2l;
    __half *Sh, *Sl, *H1h, *H1l, *H2h, *H2l;
    cudaGetSymbolAddress((void**)&Amh, d_Amh); cudaGetSymbolAddress((void**)&Aml, d_Aml);
    cudaGetSymbolAddress((void**)&Fh, d_Fh);   cudaGetSymbolAddress((void**)&Fl, d_Fl);
    cudaGetSymbolAddress((void**)&W0h, d_W0h); cudaGetSymbolAddress((void**)&W0l, d_W0l);
    cudaGetSymbolAddress((void**)&W1h, d_W1h); cudaGetSymbolAddress((void**)&W1l, d_W1l);
    cudaGetSymbolAddress((void**)&W2h, d_W2h); cudaGetSymbolAddress((void**)&W2l, d_W2l);
    cudaGetSymbolAddress((void**)&Sh, d_Sh);   cudaGetSymbolAddress((void**)&Sl, d_Sl);
    cudaGetSymbolAddress((void**)&H1h, d_H1h); cudaGetSymbolAddress((void**)&H1l, d_H1l);
    cudaGetSymbolAddress((void**)&H2h, d_H2h); cudaGetSymbolAddress((void**)&H2l, d_H2l);

    // prep
    mask_kernel<<<(NNODE * NNODE + 255) / 256, 256>>>(raw);
    {
        size_t t4 = (size_t)BATCH * NNODE * NNODE / 4;
        amask_split_kernel<<<(unsigned)((t4 + 255) / 256), 256>>>(adj);
    }
    {
        size_t t4 = (size_t)BATCH * NNODE * INC / 4;
        feat_split_kernel<<<(unsigned)((t4 + 255) / 256), 256>>>(features);
    }
    w_split_kernel<<<(INC * HIDC / 4 + 255) / 256, 256>>>(W0, W0h, W0l, INC * HIDC / 4);
    w_split_kernel<<<(HIDC * HIDC / 4 + 255) / 256, 256>>>(W1, W1h, W1l, HIDC * HIDC / 4);
    w_split_kernel<<<(HIDC * HIDC / 4 + 255) / 256, 256>>>(W2, W2h, W2l, HIDC * HIDC / 4);

    dim3 gF(2, (BATCH * NNODE) / 128);   // (2, 800)
    dim3 gA(2, 2, BATCH);                // (ntile, mtile, batch)

    tc_feat<<<gF, 256>>>(Fh, Fl, W0h, W0l, Sh, Sl, INC);
    tc_adj <<<gA, 256>>>(Amh, Aml, Sh, Sl, H1h, H1l);

    tc_feat<<<gF, 256>>>(H1h, H1l, W1h, W1l, Sh, Sl, HIDC);
    tc_adj <<<gA, 256>>>(Amh, Aml, Sh, Sl, H2h, H2l);

    tc_feat<<<gF, 256>>>(H2h, H2l, W2h, W2l, Sh, Sl, HIDC);
    tc_adj <<<gA, 256>>>(Amh, Aml, Sh, Sl, H1h, H1l);

    readout_kernel<<<BATCH, 256>>>(H1h, H1l, pw, pb, out);
}

// round 5
// speedup vs baseline: 3.7985x; 1.0059x over previous
#include <cuda_runtime.h>
#include <cuda_fp16.h>
#include <cstdint>
#include <math.h>

#define BATCH 512
#define NNODE 200
#define INC   200
#define HIDC  256
#define NVARS 2

// ---------------- scratch (fp16 hi/lo pairs) -------------------------------
__device__ float  d_mask[NNODE * NNODE];
__device__ __half d_Amh[(size_t)BATCH * NNODE * NNODE];
__device__ __half d_Aml[(size_t)BATCH * NNODE * NNODE];
__device__ __half d_Fh [(size_t)BATCH * NNODE * INC];
__device__ __half d_Fl [(size_t)BATCH * NNODE * INC];
__device__ __half d_W0h[INC * HIDC],  d_W0l[INC * HIDC];
__device__ __half d_W1h[HIDC * HIDC], d_W1l[HIDC * HIDC];
__device__ __half d_W2h[HIDC * HIDC], d_W2l[HIDC * HIDC];
__device__ __half d_Sh [(size_t)BATCH * NNODE * HIDC], d_Sl [(size_t)BATCH * NNODE * HIDC];
__device__ __half d_H1h[(size_t)BATCH * NNODE * HIDC], d_H1l[(size_t)BATCH * NNODE * HIDC];
__device__ __half d_H2h[(size_t)BATCH * NNODE * HIDC], d_H2l[(size_t)BATCH * NNODE * HIDC];

// ---------------- smem stage layout (bytes), BK = 32 ------------------------
// A: 2 k16-subtiles, each 128 rows x 16 halfs (32B) @ 48B stride (conflict-free ldmatrix)
// B: 32 k-rows x 128 n halfs, row 256B, 16B-chunk swizzle c ^= (k&7)
#define ST_AHI 0
#define ST_ALO 12288
#define ST_BHI 24576
#define ST_BLO 32768
#define STAGE  40960
#define SMEM_TOTAL (2 * STAGE)   // 81920

// ---------------- asm helpers ----------------------------------------------
__device__ __forceinline__ uint32_t cvta_s(const void* p) {
    uint32_t a;
    asm("{ .reg .u64 t; cvta.to.shared.u64 t, %1; cvt.u32.u64 %0, t; }" : "=r"(a) : "l"(p));
    return a;
}
__device__ __forceinline__ void cpa16(uint32_t dst, const void* src, uint32_t sz) {
    asm volatile("cp.async.cg.shared.global [%0], [%1], 16, %2;"
                 :: "r"(dst), "l"(src), "r"(sz));
}
#define CPA_COMMIT() asm volatile("cp.async.commit_group;" ::: "memory")
#define CPA_WAIT_ALL() asm volatile("cp.async.wait_group 0;" ::: "memory")

__device__ __forceinline__ void ldmx4(uint32_t a, uint32_t* r) {
    asm volatile("ldmatrix.sync.aligned.m8n8.x4.shared.b16 {%0,%1,%2,%3}, [%4];"
                 : "=r"(r[0]), "=r"(r[1]), "=r"(r[2]), "=r"(r[3]) : "r"(a));
}
__device__ __forceinline__ void ldmx4t(uint32_t a, uint32_t* r) {
    asm volatile("ldmatrix.sync.aligned.m8n8.x4.trans.shared.b16 {%0,%1,%2,%3}, [%4];"
                 : "=r"(r[0]), "=r"(r[1]), "=r"(r[2]), "=r"(r[3]) : "r"(a));
}
__device__ __forceinline__ void mma16816(float* c, const uint32_t* a, const uint32_t* b) {
    asm volatile(
        "mma.sync.aligned.m16n8k16.row.col.f32.f16.f16.f32 "
        "{%0,%1,%2,%3}, {%4,%5,%6,%7}, {%8,%9}, {%0,%1,%2,%3};"
        : "+f"(c[0]), "+f"(c[1]), "+f"(c[2]), "+f"(c[3])
        : "r"(a[0]), "r"(a[1]), "r"(a[2]), "r"(a[3]), "r"(b[0]), "r"(b[1]));
}

__device__ __forceinline__ void split2(float a, float b, uint32_t& hi, uint32_t& lo) {
    __half ha = __float2half_rn(a), hb = __float2half_rn(b);
    __half la = __float2half_rn(a - __half2float(ha));
    __half lb = __float2half_rn(b - __half2float(hb));
    hi = (uint32_t)__half_as_ushort(ha) | ((uint32_t)__half_as_ushort(hb) << 16);
    lo = (uint32_t)__half_as_ushort(la) | ((uint32_t)__half_as_ushort(lb) << 16);
}

// one BK=32 stage: 2 k16 sub-stages, each 12 ldmatrix + 48 MMAs per warp
__device__ __forceinline__ void mma_stage32(uint32_t st, int warp_m, int warp_n, int lane,
                                            float acc[2][8][4]) {
#pragma unroll
    for (int s = 0; s < 2; s++) {
        uint32_t bhi[8][2], blo[8][2];
        int krow = s * 16 + (lane & 15);
        int csel = (lane >> 4) & 1;
#pragma unroll
        for (int jj = 0; jj < 4; jj++) {
            int cn = (warp_n >> 3) + jj * 2 + csel;
            uint32_t off = (uint32_t)(krow * 256 + ((cn ^ (krow & 7)) << 4));
            uint32_t r[4];
            ldmx4t(st + ST_BHI + off, r);
            bhi[jj*2][0] = r[0]; bhi[jj*2][1] = r[1];
            bhi[jj*2+1][0] = r[2]; bhi[jj*2+1][1] = r[3];
            ldmx4t(st + ST_BLO + off, r);
            blo[jj*2][0] = r[0]; blo[jj*2][1] = r[1];
            blo[jj*2+1][0] = r[2]; blo[jj*2+1][1] = r[3];
        }
#pragma unroll
        for (int i = 0; i < 2; i++) {
            uint32_t ao = (uint32_t)(s * 6144 + (warp_m + i * 16 + (lane & 15)) * 48
                                     + ((lane & 16) ? 16 : 0));
            uint32_t ahi[4], alo[4];
            ldmx4(st + ST_AHI + ao, ahi);
            ldmx4(st + ST_ALO + ao, alo);
#pragma unroll
            for (int j = 0; j < 8; j++) {
                mma16816(acc[i][j], ahi, bhi[j]);
                mma16816(acc[i][j], ahi, blo[j]);
                mma16816(acc[i][j], alo, bhi[j]);
            }
        }
    }
}

__device__ __forceinline__ void epilogue_hl(__half* __restrict__ Ch, __half* __restrict__ Cl,
                                            int m0, int n0, int warp_m, int warp_n, int lane,
                                            int Mvalid, float acc[2][8][4]) {
    int g = lane >> 2, t = lane & 3;
#pragma unroll
    for (int i = 0; i < 2; i++) {
#pragma unroll
        for (int j = 0; j < 8; j++) {
            int row = m0 + warp_m + i * 16 + g;
            int col = n0 + warp_n + j * 8 + 2 * t;
            if (row < Mvalid) {
                uint32_t h, l;
                split2(acc[i][j][0], acc[i][j][1], h, l);
                *(uint32_t*)&Ch[(size_t)row * HIDC + col] = h;
                *(uint32_t*)&Cl[(size_t)row * HIDC + col] = l;
            }
            if (row + 8 < Mvalid) {
                uint32_t h, l;
                split2(acc[i][j][2], acc[i][j][3], h, l);
                *(uint32_t*)&Ch[(size_t)(row + 8) * HIDC + col] = h;
                *(uint32_t*)&Cl[(size_t)(row + 8) * HIDC + col] = l;
            }
        }
    }
}

// ---------------------------------------------------------------------------
// unified GEMM body. MGUARD: clamp A rows / C rows to Mvalid (adj); feat passes big.
// ---------------------------------------------------------------------------
template <bool MGUARD>
__device__ __forceinline__ void gemm_body(
    const __half* __restrict__ Ah, const __half* __restrict__ Al,
    const __half* __restrict__ Bh, const __half* __restrict__ Bl,
    __half* __restrict__ Ch, __half* __restrict__ Cl,
    int K, int Mvalid, int m0, int n0, uint32_t sb0)
{
    int tid = threadIdx.x, lane = tid & 31, wid = tid >> 5;
    int warp_m = (wid >> 1) * 32, warp_n = (wid & 1) * 64;
    int nch = (K + 31) >> 5;

    float acc[2][8][4];
#pragma unroll
    for (int i = 0; i < 2; i++)
#pragma unroll
        for (int j = 0; j < 8; j++)
#pragma unroll
            for (int q = 0; q < 4; q++) acc[i][j][q] = 0.0f;

    const int arow = tid >> 1, asel = tid & 1;
    const int bkr = tid >> 3, bc0 = (tid & 7) << 1;
    const int gm = m0 + arow;
    const bool mrow_ok = !MGUARD || (gm < Mvalid);

    auto load_stage = [&](int ch, uint32_t st) {
        int kc = ch << 5;
        // A: 2 granules hi + 2 lo
        size_t abase = (size_t)gm * K + kc + asel * 16;
        uint32_t adst = st + asel * 6144 + arow * 48;
#pragma unroll
        for (int q = 0; q < 2; q++) {
            uint32_t sz = (mrow_ok && (kc + asel * 16 + q * 8 < K)) ? 16u : 0u;
            cpa16(adst + ST_AHI + q * 16, Ah + abase + q * 8, sz);
            cpa16(adst + ST_ALO + q * 16, Al + abase + q * 8, sz);
        }
        // B: 2 granules hi + 2 lo
        size_t bbase = (size_t)(kc + bkr) * HIDC + n0;
        uint32_t szb = (kc + bkr < K) ? 16u : 0u;
#pragma unroll
        for (int q = 0; q < 2; q++) {
            int c = bc0 + q;
            uint32_t off = (uint32_t)(bkr * 256 + ((c ^ (bkr & 7)) << 4));
            cpa16(st + ST_BHI + off, Bh + bbase + c * 8, szb);
            cpa16(st + ST_BLO + off, Bl + bbase + c * 8, szb);
        }
    };

    load_stage(0, sb0);
    CPA_COMMIT();

    for (int ch = 0; ch < nch; ch++) {
        CPA_WAIT_ALL();
        __syncthreads();
        if (ch + 1 < nch) {
            load_stage(ch + 1, sb0 + (uint32_t)((ch + 1) & 1) * STAGE);
            CPA_COMMIT();
        }
        mma_stage32(sb0 + (uint32_t)(ch & 1) * STAGE, warp_m, warp_n, lane, acc);
    }

    epilogue_hl(Ch, Cl, m0, n0, warp_m, warp_n, lane, MGUARD ? Mvalid : (1 << 30), acc);
}

// ---------------------------------------------------------------------------
__global__ __launch_bounds__(256, 2) void tc_feat(
    const __half* __restrict__ Ah, const __half* __restrict__ Al,
    const __half* __restrict__ Bh, const __half* __restrict__ Bl,
    __half* __restrict__ Ch, __half* __restrict__ Cl, int K)
{
    extern __shared__ __align__(16) char smem[];
    uint32_t sb0 = cvta_s(smem);
    gemm_body<false>(Ah, Al, Bh, Bl, Ch, Cl, K, 1 << 30,
                     blockIdx.y * 128, blockIdx.x * 128, sb0);
}

__global__ __launch_bounds__(256, 2) void tc_adj(
    const __half* __restrict__ Amh, const __half* __restrict__ Aml,
    const __half* __restrict__ Sh,  const __half* __restrict__ Sl,
    __half* __restrict__ Hh, __half* __restrict__ Hl)
{
    extern __shared__ __align__(16) char smem[];
    uint32_t sb0 = cvta_s(smem);
    int z = blockIdx.z;
    gemm_body<true>(Amh + (size_t)z * NNODE * NNODE, Aml + (size_t)z * NNODE * NNODE,
                    Sh + (size_t)z * NNODE * HIDC,   Sl + (size_t)z * NNODE * HIDC,
                    Hh + (size_t)z * NNODE * HIDC,   Hl + (size_t)z * NNODE * HIDC,
                    NNODE, NNODE, blockIdx.y * 128, blockIdx.x * 128, sb0);
}

// ---------------------------------------------------------------------------
// prep kernels
// ---------------------------------------------------------------------------
__global__ void mask_kernel(const float* __restrict__ raw) {
    int i = blockIdx.x * blockDim.x + threadIdx.x;
    if (i < NNODE * NNODE) {
        int r = i / NNODE, c = i % NNODE;
        float v = 0.5f * (raw[r * NNODE + c] + raw[c * NNODE + r]);
        if (r == c) v += 1.0f;
        d_mask[i] = v;
    }
}

__device__ __forceinline__ void split4_store(const float* v, __half* Hd, __half* Ld, size_t i4) {
    uint32_t h0, l0, h1, l1;
    split2(v[0], v[1], h0, l0);
    split2(v[2], v[3], h1, l1);
    ((uint2*)Hd)[i4] = make_uint2(h0, h1);
    ((uint2*)Ld)[i4] = make_uint2(l0, l1);
}

__global__ void amask_split_kernel(const float* __restrict__ adj) {
    size_t i4 = (size_t)blockIdx.x * blockDim.x + threadIdx.x;
    if (i4 >= (size_t)BATCH * NNODE * NNODE / 4) return;
    size_t base = i4 * 4;
    int rem = (int)(base % (NNODE * NNODE));
    float4 x = *(const float4*)(adj + base);
    float4 m = *(const float4*)(d_mask + rem);
    float v[4];
    v[0] = m.x / (1.0f + __expf(-x.x));
    v[1] = m.y / (1.0f + __expf(-x.y));
    v[2] = m.z / (1.0f + __expf(-x.z));
    v[3] = m.w / (1.0f + __expf(-x.w));
    split4_store(v, d_Amh, d_Aml, i4);
}

__global__ void feat_split_kernel(const float* __restrict__ f) {
    size_t i4 = (size_t)blockIdx.x * blockDim.x + threadIdx.x;
    if (i4 >= (size_t)BATCH * NNODE * INC / 4) return;
    float4 x = *(const float4*)(f + i4 * 4);
    float v[4] = {x.x, x.y, x.z, x.w};
    split4_store(v, d_Fh, d_Fl, i4);
}

__global__ void w_split_kernel(const float* __restrict__ w, __half* __restrict__ Hd,
                               __half* __restrict__ Ld, int total4) {
    int i4 = blockIdx.x * blockDim.x + threadIdx.x;
    if (i4 >= total4) return;
    float4 x = *(const float4*)(w + (size_t)i4 * 4);
    float v[4] = {x.x, x.y, x.z, x.w};
    split4_store(v, Hd, Ld, i4);
}

// ---------------------------------------------------------------------------
__global__ __launch_bounds__(256) void readout_kernel(
    const __half* __restrict__ Hh, const __half* __restrict__ Hl,
    const float* __restrict__ pw, const float* __restrict__ pb,
    float* __restrict__ out)
{
    int b = blockIdx.x;
    int c = threadIdx.x;
    const __half* Hbh = Hh + (size_t)b * NNODE * HIDC;
    const __half* Hbl = Hl + (size_t)b * NNODE * HIDC;

    float s = 0.0f;
    for (int n = 0; n < NNODE; n++)
        s += __half2float(Hbh[n * HIDC + c]) + __half2float(Hbl[n * HIDC + c]);
    s *= (1.0f / NNODE);

    __shared__ float r0[256], r1[256];
    r0[c] = s * pw[c * NVARS + 0];
    r1[c] = s * pw[c * NVARS + 1];
    __syncthreads();
    for (int off = 128; off > 0; off >>= 1) {
        if (c < off) { r0[c] += r0[c + off]; r1[c] += r1[c + off]; }
        __syncthreads();
    }
    if (c == 0) {
        out[b * NVARS + 0] = r0[0] + pb[0];
        out[b * NVARS + 1] = r1[0] + pb[1];
    }
}

// ---------------------------------------------------------------------------
extern "C" void kernel_launch(void* const* d_in, const int* in_sizes, int n_in,
                              void* d_out, int out_size)
{
    const float* adj      = (const float*)d_in[0];
    const float* features = (const float*)d_in[1];
    const float* raw      = (const float*)d_in[2];
    const float* W0       = (const float*)d_in[3];
    const float* W1       = (const float*)d_in[4];
    const float* W2       = (const float*)d_in[5];
    const float* pw       = (const float*)d_in[6];
    const float* pb       = (const float*)d_in[7];
    float* out = (float*)d_out;

    static int smem_set = 0;
    cudaFuncSetAttribute(tc_feat, cudaFuncAttributeMaxDynamicSharedMemorySize, SMEM_TOTAL);
    cudaFuncSetAttribute(tc_adj,  cudaFuncAttributeMaxDynamicSharedMemorySize, SMEM_TOTAL);
    (void)smem_set;

    __half *Amh, *Aml, *Fh, *Fl, *W0h, *W0l, *W1h, *W1l, *W2h, *W2l;
    __half *Sh, *Sl, *H1h, *H1l, *H2h, *H2l;
    cudaGetSymbolAddress((void**)&Amh, d_Amh); cudaGetSymbolAddress((void**)&Aml, d_Aml);
    cudaGetSymbolAddress((void**)&Fh, d_Fh);   cudaGetSymbolAddress((void**)&Fl, d_Fl);
    cudaGetSymbolAddress((void**)&W0h, d_W0h); cudaGetSymbolAddress((void**)&W0l, d_W0l);
    cudaGetSymbolAddress((void**)&W1h, d_W1h); cudaGetSymbolAddress((void**)&W1l, d_W1l);
    cudaGetSymbolAddress((void**)&W2h, d_W2h); cudaGetSymbolAddress((void**)&W2l, d_W2l);
    cudaGetSymbolAddress((void**)&Sh, d_Sh);   cudaGetSymbolAddress((void**)&Sl, d_Sl);
    cudaGetSymbolAddress((void**)&H1h, d_H1h); cudaGetSymbolAddress((void**)&H1l, d_H1l);
    cudaGetSymbolAddress((void**)&H2h, d_H2h); cudaGetSymbolAddress((void**)&H2l, d_H2l);

    // prep
    mask_kernel<<<(NNODE * NNODE + 255) / 256, 256>>>(raw);
    {
        size_t t4 = (size_t)BATCH * NNODE * NNODE / 4;
        amask_split_kernel<<<(unsigned)((t4 + 255) / 256), 256>>>(adj);
    }
    {
        size_t t4 = (size_t)BATCH * NNODE * INC / 4;
        feat_split_kernel<<<(unsigned)((t4 + 255) / 256), 256>>>(features);
    }
    w_split_kernel<<<(INC * HIDC / 4 + 255) / 256, 256>>>(W0, W0h, W0l, INC * HIDC / 4);
    w_split_kernel<<<(HIDC * HIDC / 4 + 255) / 256, 256>>>(W1, W1h, W1l, HIDC * HIDC / 4);
    w_split_kernel<<<(HIDC * HIDC / 4 + 255) / 256, 256>>>(W2, W2h, W2l, HIDC * HIDC / 4);

    dim3 gF(2, (BATCH * NNODE) / 128);   // (2, 800)
    dim3 gA(2, 2, BATCH);                // (ntile, mtile, batch)

    tc_feat<<<gF, 256, SMEM_TOTAL>>>(Fh, Fl, W0h, W0l, Sh, Sl, INC);
    tc_adj <<<gA, 256, SMEM_TOTAL>>>(Amh, Aml, Sh, Sl, H1h, H1l);

    tc_feat<<<gF, 256, SMEM_TOTAL>>>(H1h, H1l, W1h, W1l, Sh, Sl, HIDC);
    tc_adj <<<gA, 256, SMEM_TOTAL>>>(Amh, Aml, Sh, Sl, H2h, H2l);

    tc_feat<<<gF, 256, SMEM_TOTAL>>>(H2h, H2l, W2h, W2l, Sh, Sl, HIDC);
    tc_adj <<<gA, 256, SMEM_TOTAL>>>(Amh, Aml, Sh, Sl, H1h, H1l);

    readout_kernel<<<BATCH, 256>>>(H1h, H1l, pw, pb, out);
}

// round 6
// speedup vs baseline: 3.8876x; 1.0235x over previous
#include <cuda_runtime.h>
#include <cuda_fp16.h>
#include <cstdint>
#include <math.h>

#define BATCH 512
#define NNODE 200
#define INC   200
#define HIDC  256
#define NVARS 2

// ---------------- scratch (fp16 hi/lo pairs) -------------------------------
__device__ float  d_mask[NNODE * NNODE];
__device__ __half d_Amh[(size_t)BATCH * NNODE * NNODE];
__device__ __half d_Aml[(size_t)BATCH * NNODE * NNODE];
__device__ __half d_Fh [(size_t)BATCH * NNODE * INC];
__device__ __half d_Fl [(size_t)BATCH * NNODE * INC];
__device__ __half d_W0h[INC * HIDC],  d_W0l[INC * HIDC];
__device__ __half d_W1h[HIDC * HIDC], d_W1l[HIDC * HIDC];
__device__ __half d_W2h[HIDC * HIDC], d_W2l[HIDC * HIDC];
__device__ __half d_Sh [(size_t)BATCH * NNODE * HIDC], d_Sl [(size_t)BATCH * NNODE * HIDC];
__device__ __half d_H1h[(size_t)BATCH * NNODE * HIDC], d_H1l[(size_t)BATCH * NNODE * HIDC];
__device__ __half d_H2h[(size_t)BATCH * NNODE * HIDC], d_H2l[(size_t)BATCH * NNODE * HIDC];

// ---------------- smem stage layout (bytes), BK = 32 ------------------------
#define ST_AHI 0
#define ST_ALO 12288
#define ST_BHI 24576
#define ST_BLO 32768
#define STAGE  40960
#define SMEM_TOTAL (2 * STAGE)   // 81920

// ---------------- asm helpers ----------------------------------------------
__device__ __forceinline__ uint32_t cvta_s(const void* p) {
    uint32_t a;
    asm("{ .reg .u64 t; cvta.to.shared.u64 t, %1; cvt.u32.u64 %0, t; }" : "=r"(a) : "l"(p));
    return a;
}
__device__ __forceinline__ void cpa16(uint32_t dst, const void* src, uint32_t sz) {
    asm volatile("cp.async.cg.shared.global [%0], [%1], 16, %2;"
                 :: "r"(dst), "l"(src), "r"(sz));
}
#define CPA_COMMIT() asm volatile("cp.async.commit_group;" ::: "memory")
#define CPA_WAIT_ALL() asm volatile("cp.async.wait_group 0;" ::: "memory")

__device__ __forceinline__ void ldmx4(uint32_t a, uint32_t* r) {
    asm volatile("ldmatrix.sync.aligned.m8n8.x4.shared.b16 {%0,%1,%2,%3}, [%4];"
                 : "=r"(r[0]), "=r"(r[1]), "=r"(r[2]), "=r"(r[3]) : "r"(a));
}
__device__ __forceinline__ void ldmx4t(uint32_t a, uint32_t* r) {
    asm volatile("ldmatrix.sync.aligned.m8n8.x4.trans.shared.b16 {%0,%1,%2,%3}, [%4];"
                 : "=r"(r[0]), "=r"(r[1]), "=r"(r[2]), "=r"(r[3]) : "r"(a));
}
__device__ __forceinline__ void mma16816(float* c, const uint32_t* a, const uint32_t* b) {
    asm volatile(
        "mma.sync.aligned.m16n8k16.row.col.f32.f16.f16.f32 "
        "{%0,%1,%2,%3}, {%4,%5,%6,%7}, {%8,%9}, {%0,%1,%2,%3};"
        : "+f"(c[0]), "+f"(c[1]), "+f"(c[2]), "+f"(c[3])
        : "r"(a[0]), "r"(a[1]), "r"(a[2]), "r"(a[3]), "r"(b[0]), "r"(b[1]));
}

__device__ __forceinline__ void split2(float a, float b, uint32_t& hi, uint32_t& lo) {
    __half ha = __float2half_rn(a), hb = __float2half_rn(b);
    __half la = __float2half_rn(a - __half2float(ha));
    __half lb = __float2half_rn(b - __half2float(hb));
    hi = (uint32_t)__half_as_ushort(ha) | ((uint32_t)__half_as_ushort(hb) << 16);
    lo = (uint32_t)__half_as_ushort(la) | ((uint32_t)__half_as_ushort(lb) << 16);
}

// one BK=32 stage; ksubs = # valid k16 sub-stages (1 or 2),
// mfrags = # valid m16 fragments for this warp (0..2, 0 => skip warp)
__device__ __forceinline__ void mma_stage32(uint32_t st, int warp_m, int warp_n, int lane,
                                            float acc[2][8][4], int mfrags, int ksubs) {
    if (mfrags == 0) return;
#pragma unroll
    for (int s = 0; s < 2; s++) {
        if (s >= ksubs) break;
        uint32_t bhi[8][2], blo[8][2];
        int krow = s * 16 + (lane & 15);
        int csel = (lane >> 4) & 1;
#pragma unroll
        for (int jj = 0; jj < 4; jj++) {
            int cn = (warp_n >> 3) + jj * 2 + csel;
            uint32_t off = (uint32_t)(krow * 256 + ((cn ^ (krow & 7)) << 4));
            uint32_t r[4];
            ldmx4t(st + ST_BHI + off, r);
            bhi[jj*2][0] = r[0]; bhi[jj*2][1] = r[1];
            bhi[jj*2+1][0] = r[2]; bhi[jj*2+1][1] = r[3];
            ldmx4t(st + ST_BLO + off, r);
            blo[jj*2][0] = r[0]; blo[jj*2][1] = r[1];
            blo[jj*2+1][0] = r[2]; blo[jj*2+1][1] = r[3];
        }
#pragma unroll
        for (int i = 0; i < 2; i++) {
            if (i >= mfrags) break;
            uint32_t ao = (uint32_t)(s * 6144 + (warp_m + i * 16 + (lane & 15)) * 48
                                     + ((lane & 16) ? 16 : 0));
            uint32_t ahi[4], alo[4];
            ldmx4(st + ST_AHI + ao, ahi);
            ldmx4(st + ST_ALO + ao, alo);
#pragma unroll
            for (int j = 0; j < 8; j++) {
                mma16816(acc[i][j], ahi, bhi[j]);
                mma16816(acc[i][j], ahi, blo[j]);
                mma16816(acc[i][j], alo, bhi[j]);
            }
        }
    }
}

__device__ __forceinline__ void epilogue_hl(__half* __restrict__ Ch, __half* __restrict__ Cl,
                                            int m0, int n0, int warp_m, int warp_n, int lane,
                                            int Mvalid, float acc[2][8][4]) {
    int g = lane >> 2, t = lane & 3;
#pragma unroll
    for (int i = 0; i < 2; i++) {
#pragma unroll
        for (int j = 0; j < 8; j++) {
            int row = m0 + warp_m + i * 16 + g;
            int col = n0 + warp_n + j * 8 + 2 * t;
            if (row < Mvalid) {
                uint32_t h, l;
                split2(acc[i][j][0], acc[i][j][1], h, l);
                *(uint32_t*)&Ch[(size_t)row * HIDC + col] = h;
                *(uint32_t*)&Cl[(size_t)row * HIDC + col] = l;
            }
            if (row + 8 < Mvalid) {
                uint32_t h, l;
                split2(acc[i][j][2], acc[i][j][3], h, l);
                *(uint32_t*)&Ch[(size_t)(row + 8) * HIDC + col] = h;
                *(uint32_t*)&Cl[(size_t)(row + 8) * HIDC + col] = l;
            }
        }
    }
}

// ---------------------------------------------------------------------------
template <bool MGUARD>
__device__ __forceinline__ void gemm_body(
    const __half* __restrict__ Ah, const __half* __restrict__ Al,
    const __half* __restrict__ Bh, const __half* __restrict__ Bl,
    __half* __restrict__ Ch, __half* __restrict__ Cl,
    int K, int Mvalid, int m0, int n0, uint32_t sb0)
{
    int tid = threadIdx.x, lane = tid & 31, wid = tid >> 5;
    int warp_m = (wid >> 1) * 32, warp_n = (wid & 1) * 64;
    int k16max = (K + 15) >> 4;
    int nch = (k16max + 1) >> 1;

    int mfrags = 2;
    if (MGUARD) {
        int rem = Mvalid - m0 - warp_m;
        mfrags = (rem > 16) ? 2 : ((rem > 0) ? 1 : 0);
    }

    float acc[2][8][4];
#pragma unroll
    for (int i = 0; i < 2; i++)
#pragma unroll
        for (int j = 0; j < 8; j++)
#pragma unroll
            for (int q = 0; q < 4; q++) acc[i][j][q] = 0.0f;

    const int arow = tid >> 1, asel = tid & 1;
    const int bkr = tid >> 3, bc0 = (tid & 7) << 1;
    const int gm = m0 + arow;
    const bool mrow_ok = !MGUARD || (gm < Mvalid);

    auto load_stage = [&](int ch, uint32_t st) {
        int kc = ch << 5;
        size_t abase = (size_t)gm * K + kc + asel * 16;
        uint32_t adst = st + asel * 6144 + arow * 48;
#pragma unroll
        for (int q = 0; q < 2; q++) {
            uint32_t sz = (mrow_ok && (kc + asel * 16 + q * 8 < K)) ? 16u : 0u;
            cpa16(adst + ST_AHI + q * 16, Ah + abase + q * 8, sz);
            cpa16(adst + ST_ALO + q * 16, Al + abase + q * 8, sz);
        }
        size_t bbase = (size_t)(kc + bkr) * HIDC + n0;
        uint32_t szb = (kc + bkr < K) ? 16u : 0u;
#pragma unroll
        for (int q = 0; q < 2; q++) {
            int c = bc0 + q;
            uint32_t off = (uint32_t)(bkr * 256 + ((c ^ (bkr & 7)) << 4));
            cpa16(st + ST_BHI + off, Bh + bbase + c * 8, szb);
            cpa16(st + ST_BLO + off, Bl + bbase + c * 8, szb);
        }
    };

    load_stage(0, sb0);
    CPA_COMMIT();

    for (int ch = 0; ch < nch; ch++) {
        CPA_WAIT_ALL();
        __syncthreads();
        if (ch + 1 < nch) {
            load_stage(ch + 1, sb0 + (uint32_t)((ch + 1) & 1) * STAGE);
            CPA_COMMIT();
        }
        int ksubs = k16max - ch * 2;
        if (ksubs > 2) ksubs = 2;
        mma_stage32(sb0 + (uint32_t)(ch & 1) * STAGE, warp_m, warp_n, lane, acc, mfrags, ksubs);
    }

    epilogue_hl(Ch, Cl, m0, n0, warp_m, warp_n, lane, MGUARD ? Mvalid : (1 << 30), acc);
}

// ---------------------------------------------------------------------------
__global__ __launch_bounds__(256, 2) void tc_feat(
    const __half* __restrict__ Ah, const __half* __restrict__ Al,
    const __half* __restrict__ Bh, const __half* __restrict__ Bl,
    __half* __restrict__ Ch, __half* __restrict__ Cl, int K)
{
    extern __shared__ __align__(16) char smem[];
    uint32_t sb0 = cvta_s(smem);
    gemm_body<false>(Ah, Al, Bh, Bl, Ch, Cl, K, 1 << 30,
                     blockIdx.y * 128, blockIdx.x * 128, sb0);
}

__global__ __launch_bounds__(256, 2) void tc_adj(
    const __half* __restrict__ Amh, const __half* __restrict__ Aml,
    const __half* __restrict__ Sh,  const __half* __restrict__ Sl,
    __half* __restrict__ Hh, __half* __restrict__ Hl)
{
    extern __shared__ __align__(16) char smem[];
    uint32_t sb0 = cvta_s(smem);
    int z = blockIdx.z;
    gemm_body<true>(Amh + (size_t)z * NNODE * NNODE, Aml + (size_t)z * NNODE * NNODE,
                    Sh + (size_t)z * NNODE * HIDC,   Sl + (size_t)z * NNODE * HIDC,
                    Hh + (size_t)z * NNODE * HIDC,   Hl + (size_t)z * NNODE * HIDC,
                    NNODE, NNODE, blockIdx.y * 128, blockIdx.x * 128, sb0);
}

// ---------------------------------------------------------------------------
// prep: mask first (separate), then everything else merged into ONE kernel
// so the 6th launch overall is a GEMM (profiling visibility).
// ---------------------------------------------------------------------------
__global__ void mask_kernel(const float* __restrict__ raw) {
    int i = blockIdx.x * blockDim.x + threadIdx.x;
    if (i < NNODE * NNODE) {
        int r = i / NNODE, c = i % NNODE;
        float v = 0.5f * (raw[r * NNODE + c] + raw[c * NNODE + r]);
        if (r == c) v += 1.0f;
        d_mask[i] = v;
    }
}

__device__ __forceinline__ void split4_store(const float* v, __half* Hd, __half* Ld, size_t i4) {
    uint32_t h0, l0, h1, l1;
    split2(v[0], v[1], h0, l0);
    split2(v[2], v[3], h1, l1);
    ((uint2*)Hd)[i4] = make_uint2(h0, h1);
    ((uint2*)Ld)[i4] = make_uint2(l0, l1);
}

#define NA_Q ((size_t)BATCH * NNODE * NNODE / 4)   // 5,120,000
#define NF_Q ((size_t)BATCH * NNODE * INC / 4)     // 5,120,000
#define W0_Q (INC * HIDC / 4)                      // 12,800
#define W1_Q (HIDC * HIDC / 4)                     // 16,384
#define W2_Q (HIDC * HIDC / 4)                     // 16,384
#define TOTAL_Q (NA_Q + NF_Q + W0_Q + W1_Q + W2_Q)

__global__ __launch_bounds__(256) void prep_kernel(
    const float* __restrict__ adj, const float* __restrict__ feat,
    const float* __restrict__ W0, const float* __restrict__ W1,
    const float* __restrict__ W2)
{
    size_t gid = (size_t)blockIdx.x * 256 + threadIdx.x;
    if (gid < NA_Q) {
        size_t base = gid * 4;
        int rem = (int)(base % (NNODE * NNODE));
        float4 x = *(const float4*)(adj + base);
        float4 m = *(const float4*)(d_mask + rem);
        float v[4];
        v[0] = m.x / (1.0f + __expf(-x.x));
        v[1] = m.y / (1.0f + __expf(-x.y));
        v[2] = m.z / (1.0f + __expf(-x.z));
        v[3] = m.w / (1.0f + __expf(-x.w));
        split4_store(v, d_Amh, d_Aml, gid);
    } else if (gid < NA_Q + NF_Q) {
        size_t i4 = gid - NA_Q;
        float4 x = *(const float4*)(feat + i4 * 4);
        float v[4] = {x.x, x.y, x.z, x.w};
        split4_store(v, d_Fh, d_Fl, i4);
    } else {
        size_t i = gid - NA_Q - NF_Q;
        const float* src; __half *Hd, *Ld; size_t i4;
        if (i < W0_Q)            { src = W0; Hd = d_W0h; Ld = d_W0l; i4 = i; }
        else if (i < W0_Q + W1_Q){ src = W1; Hd = d_W1h; Ld = d_W1l; i4 = i - W0_Q; }
        else if (i < W0_Q + W1_Q + W2_Q)
                                 { src = W2; Hd = d_W2h; Ld = d_W2l; i4 = i - W0_Q - W1_Q; }
        else return;
        float4 x = *(const float4*)(src + i4 * 4);
        float v[4] = {x.x, x.y, x.z, x.w};
        split4_store(v, Hd, Ld, i4);
    }
}

// ---------------------------------------------------------------------------
__global__ __launch_bounds__(256) void readout_kernel(
    const __half* __restrict__ Hh, const __half* __restrict__ Hl,
    const float* __restrict__ pw, const float* __restrict__ pb,
    float* __restrict__ out)
{
    int b = blockIdx.x;
    int c = threadIdx.x;
    const __half* Hbh = Hh + (size_t)b * NNODE * HIDC;
    const __half* Hbl = Hl + (size_t)b * NNODE * HIDC;

    float s = 0.0f;
    for (int n = 0; n < NNODE; n++)
        s += __half2float(Hbh[n * HIDC + c]) + __half2float(Hbl[n * HIDC + c]);
    s *= (1.0f / NNODE);

    __shared__ float r0[256], r1[256];
    r0[c] = s * pw[c * NVARS + 0];
    r1[c] = s * pw[c * NVARS + 1];
    __syncthreads();
    for (int off = 128; off > 0; off >>= 1) {
        if (c < off) { r0[c] += r0[c + off]; r1[c] += r1[c + off]; }
        __syncthreads();
    }
    if (c == 0) {
        out[b * NVARS + 0] = r0[0] + pb[0];
        out[b * NVARS + 1] = r1[0] + pb[1];
    }
}

// ---------------------------------------------------------------------------
extern "C" void kernel_launch(void* const* d_in, const int* in_sizes, int n_in,
                              void* d_out, int out_size)
{
    const float* adj      = (const float*)d_in[0];
    const float* features = (const float*)d_in[1];
    const float* raw      = (const float*)d_in[2];
    const float* W0       = (const float*)d_in[3];
    const float* W1       = (const float*)d_in[4];
    const float* W2       = (const float*)d_in[5];
    const float* pw       = (const float*)d_in[6];
    const float* pb       = (const float*)d_in[7];
    float* out = (float*)d_out;

    cudaFuncSetAttribute(tc_feat, cudaFuncAttributeMaxDynamicSharedMemorySize, SMEM_TOTAL);
    cudaFuncSetAttribute(tc_adj,  cudaFuncAttributeMaxDynamicSharedMemorySize, SMEM_TOTAL);

    __half *Amh, *Aml, *Fh, *Fl, *W0h, *W0l, *W1h, *W1l, *W2h, *W2l;
    __half *Sh, *Sl, *H1h, *H1l, *H2h, *H2l;
    cudaGetSymbolAddress((void**)&Amh, d_Amh); cudaGetSymbolAddress((void**)&Aml, d_Aml);
    cudaGetSymbolAddress((void**)&Fh, d_Fh);   cudaGetSymbolAddress((void**)&Fl, d_Fl);
    cudaGetSymbolAddress((void**)&W0h, d_W0h); cudaGetSymbolAddress((void**)&W0l, d_W0l);
    cudaGetSymbolAddress((void**)&W1h, d_W1h); cudaGetSymbolAddress((void**)&W1l, d_W1l);
    cudaGetSymbolAddress((void**)&W2h, d_W2h); cudaGetSymbolAddress((void**)&W2l, d_W2l);
    cudaGetSymbolAddress((void**)&Sh, d_Sh);   cudaGetSymbolAddress((void**)&Sl, d_Sl);
    cudaGetSymbolAddress((void**)&H1h, d_H1h); cudaGetSymbolAddress((void**)&H1l, d_H1l);
    cudaGetSymbolAddress((void**)&H2h, d_H2h); cudaGetSymbolAddress((void**)&H2l, d_H2l);

    // launch 1: mask; launch 2: merged prep
    mask_kernel<<<(NNODE * NNODE + 255) / 256, 256>>>(raw);
    prep_kernel<<<(unsigned)((TOTAL_Q + 255) / 256), 256>>>(adj, features, W0, W1, W2);

    dim3 gF(2, (BATCH * NNODE) / 128);   // (2, 800)
    dim3 gA(2, 2, BATCH);                // (ntile, mtile, batch)

    // launches 3..8: GEMMs (6th overall = tc_adj of layer 1)
    tc_feat<<<gF, 256, SMEM_TOTAL>>>(Fh, Fl, W0h, W0l, Sh, Sl, INC);
    tc_adj <<<gA, 256, SMEM_TOTAL>>>(Amh, Aml, Sh, Sl, H1h, H1l);

    tc_feat<<<gF, 256, SMEM_TOTAL>>>(H1h, H1l, W1h, W1l, Sh, Sl, HIDC);
    tc_adj <<<gA, 256, SMEM_TOTAL>>>(Amh, Aml, Sh, Sl, H2h, H2l);

    tc_feat<<<gF, 256, SMEM_TOTAL>>>(H2h, H2l, W2h, W2l, Sh, Sl, HIDC);
    tc_adj <<<gA, 256, SMEM_TOTAL>>>(Amh, Aml, Sh, Sl, H1h, H1l);

    readout_kernel<<<BATCH, 256>>>(H1h, H1l, pw, pb, out);
}

// round 7
// speedup vs baseline: 3.9004x; 1.0033x over previous
#include <cuda_runtime.h>
#include <cuda_fp16.h>
#include <cstdint>
#include <math.h>

#define BATCH 512
#define NNODE 200
#define INC   200
#define HIDC  256
#define NVARS 2

// ---------------- scratch (fp16 hi/lo pairs) -------------------------------
__device__ float  d_mask[NNODE * NNODE];
__device__ __half d_Amh[(size_t)BATCH * NNODE * NNODE];
__device__ __half d_Aml[(size_t)BATCH * NNODE * NNODE];
__device__ __half d_Fh [(size_t)BATCH * NNODE * INC];
__device__ __half d_Fl [(size_t)BATCH * NNODE * INC];
__device__ __half d_W0h[INC * HIDC],  d_W0l[INC * HIDC];
__device__ __half d_W1h[HIDC * HIDC], d_W1l[HIDC * HIDC];
__device__ __half d_W2h[HIDC * HIDC], d_W2l[HIDC * HIDC];
__device__ __half d_Sh [(size_t)BATCH * NNODE * HIDC], d_Sl [(size_t)BATCH * NNODE * HIDC];
__device__ __half d_H1h[(size_t)BATCH * NNODE * HIDC], d_H1l[(size_t)BATCH * NNODE * HIDC];
__device__ __half d_H2h[(size_t)BATCH * NNODE * HIDC], d_H2l[(size_t)BATCH * NNODE * HIDC];

// ---------------- smem stage layout (bytes), BK = 32 ------------------------
#define ST_AHI 0
#define ST_ALO 12288
#define ST_BHI 24576
#define ST_BLO 32768
#define STAGE  40960
#define SMEM_TOTAL (2 * STAGE)   // 81920

// ---------------- asm helpers ----------------------------------------------
__device__ __forceinline__ uint32_t cvta_s(const void* p) {
    uint32_t a;
    asm("{ .reg .u64 t; cvta.to.shared.u64 t, %1; cvt.u32.u64 %0, t; }" : "=r"(a) : "l"(p));
    return a;
}
__device__ __forceinline__ void cpa16(uint32_t dst, const void* src, uint32_t sz) {
    asm volatile("cp.async.cg.shared.global [%0], [%1], 16, %2;"
                 :: "r"(dst), "l"(src), "r"(sz));
}
#define CPA_COMMIT() asm volatile("cp.async.commit_group;" ::: "memory")
#define CPA_WAIT_ALL() asm volatile("cp.async.wait_group 0;" ::: "memory")

__device__ __forceinline__ void ldmx4(uint32_t a, uint32_t* r) {
    asm volatile("ldmatrix.sync.aligned.m8n8.x4.shared.b16 {%0,%1,%2,%3}, [%4];"
                 : "=r"(r[0]), "=r"(r[1]), "=r"(r[2]), "=r"(r[3]) : "r"(a));
}
__device__ __forceinline__ void ldmx4t(uint32_t a, uint32_t* r) {
    asm volatile("ldmatrix.sync.aligned.m8n8.x4.trans.shared.b16 {%0,%1,%2,%3}, [%4];"
                 : "=r"(r[0]), "=r"(r[1]), "=r"(r[2]), "=r"(r[3]) : "r"(a));
}
__device__ __forceinline__ void mma16816(float* c, const uint32_t* a, const uint32_t* b) {
    asm volatile(
        "mma.sync.aligned.m16n8k16.row.col.f32.f16.f16.f32 "
        "{%0,%1,%2,%3}, {%4,%5,%6,%7}, {%8,%9}, {%0,%1,%2,%3};"
        : "+f"(c[0]), "+f"(c[1]), "+f"(c[2]), "+f"(c[3])
        : "r"(a[0]), "r"(a[1]), "r"(a[2]), "r"(a[3]), "r"(b[0]), "r"(b[1]));
}

__device__ __forceinline__ void split2(float a, float b, uint32_t& hi, uint32_t& lo) {
    __half ha = __float2half_rn(a), hb = __float2half_rn(b);
    __half la = __float2half_rn(a - __half2float(ha));
    __half lb = __float2half_rn(b - __half2float(hb));
    hi = (uint32_t)__half_as_ushort(ha) | ((uint32_t)__half_as_ushort(hb) << 16);
    lo = (uint32_t)__half_as_ushort(la) | ((uint32_t)__half_as_ushort(lb) << 16);
}

// one BK=32 stage; term-major j-passes -> RAW distance 8 on each accumulator
__device__ __forceinline__ void mma_stage32(uint32_t st, int warp_m, int warp_n, int lane,
                                            float acc[2][8][4], int mfrags, int ksubs) {
    if (mfrags == 0) return;
#pragma unroll
    for (int s = 0; s < 2; s++) {
        if (s >= ksubs) break;
        uint32_t bhi[8][2], blo[8][2];
        int krow = s * 16 + (lane & 15);
        int csel = (lane >> 4) & 1;
#pragma unroll
        for (int jj = 0; jj < 4; jj++) {
            int cn = (warp_n >> 3) + jj * 2 + csel;
            uint32_t off = (uint32_t)(krow * 256 + ((cn ^ (krow & 7)) << 4));
            uint32_t r[4];
            ldmx4t(st + ST_BHI + off, r);
            bhi[jj*2][0] = r[0]; bhi[jj*2][1] = r[1];
            bhi[jj*2+1][0] = r[2]; bhi[jj*2+1][1] = r[3];
            ldmx4t(st + ST_BLO + off, r);
            blo[jj*2][0] = r[0]; blo[jj*2][1] = r[1];
            blo[jj*2+1][0] = r[2]; blo[jj*2+1][1] = r[3];
        }
#pragma unroll
        for (int i = 0; i < 2; i++) {
            if (i >= mfrags) break;
            uint32_t ao = (uint32_t)(s * 6144 + (warp_m + i * 16 + (lane & 15)) * 48
                                     + ((lane & 16) ? 16 : 0));
            uint32_t ahi[4], alo[4];
            ldmx4(st + ST_AHI + ao, ahi);
            ldmx4(st + ST_ALO + ao, alo);
            // pass 1: hh  (8 independent MMAs)
#pragma unroll
            for (int j = 0; j < 8; j++) mma16816(acc[i][j], ahi, bhi[j]);
            // pass 2: hl
#pragma unroll
            for (int j = 0; j < 8; j++) mma16816(acc[i][j], ahi, blo[j]);
            // pass 3: lh
#pragma unroll
            for (int j = 0; j < 8; j++) mma16816(acc[i][j], alo, bhi[j]);
        }
    }
}

__device__ __forceinline__ void epilogue_hl(__half* __restrict__ Ch, __half* __restrict__ Cl,
                                            int m0, int n0, int warp_m, int warp_n, int lane,
                                            int Mvalid, float acc[2][8][4]) {
    int g = lane >> 2, t = lane & 3;
#pragma unroll
    for (int i = 0; i < 2; i++) {
#pragma unroll
        for (int j = 0; j < 8; j++) {
            int row = m0 + warp_m + i * 16 + g;
            int col = n0 + warp_n + j * 8 + 2 * t;
            if (row < Mvalid) {
                uint32_t h, l;
                split2(acc[i][j][0], acc[i][j][1], h, l);
                *(uint32_t*)&Ch[(size_t)row * HIDC + col] = h;
                *(uint32_t*)&Cl[(size_t)row * HIDC + col] = l;
            }
            if (row + 8 < Mvalid) {
                uint32_t h, l;
                split2(acc[i][j][2], acc[i][j][3], h, l);
                *(uint32_t*)&Ch[(size_t)(row + 8) * HIDC + col] = h;
                *(uint32_t*)&Cl[(size_t)(row + 8) * HIDC + col] = l;
            }
        }
    }
}

// ---------------------------------------------------------------------------
template <bool MGUARD>
__device__ __forceinline__ void gemm_body(
    const __half* __restrict__ Ah, const __half* __restrict__ Al,
    const __half* __restrict__ Bh, const __half* __restrict__ Bl,
    __half* __restrict__ Ch, __half* __restrict__ Cl,
    int K, int Mvalid, int m0, int n0, uint32_t sb0)
{
    int tid = threadIdx.x, lane = tid & 31, wid = tid >> 5;
    int warp_m = (wid >> 1) * 32, warp_n = (wid & 1) * 64;
    int k16max = (K + 15) >> 4;
    int nch = (k16max + 1) >> 1;

    int mfrags = 2;
    if (MGUARD) {
        int rem = Mvalid - m0 - warp_m;
        mfrags = (rem > 16) ? 2 : ((rem > 0) ? 1 : 0);
    }

    float acc[2][8][4];
#pragma unroll
    for (int i = 0; i < 2; i++)
#pragma unroll
        for (int j = 0; j < 8; j++)
#pragma unroll
            for (int q = 0; q < 4; q++) acc[i][j][q] = 0.0f;

    const int arow = tid >> 1, asel = tid & 1;
    const int bkr = tid >> 3, bc0 = (tid & 7) << 1;
    const int gm = m0 + arow;
    const bool mrow_ok = !MGUARD || (gm < Mvalid);

    auto load_stage = [&](int ch, uint32_t st) {
        int kc = ch << 5;
        size_t abase = (size_t)gm * K + kc + asel * 16;
        uint32_t adst = st + asel * 6144 + arow * 48;
#pragma unroll
        for (int q = 0; q < 2; q++) {
            uint32_t sz = (mrow_ok && (kc + asel * 16 + q * 8 < K)) ? 16u : 0u;
            cpa16(adst + ST_AHI + q * 16, Ah + abase + q * 8, sz);
            cpa16(adst + ST_ALO + q * 16, Al + abase + q * 8, sz);
        }
        size_t bbase = (size_t)(kc + bkr) * HIDC + n0;
        uint32_t szb = (kc + bkr < K) ? 16u : 0u;
#pragma unroll
        for (int q = 0; q < 2; q++) {
            int c = bc0 + q;
            uint32_t off = (uint32_t)(bkr * 256 + ((c ^ (bkr & 7)) << 4));
            cpa16(st + ST_BHI + off, Bh + bbase + c * 8, szb);
            cpa16(st + ST_BLO + off, Bl + bbase + c * 8, szb);
        }
    };

    load_stage(0, sb0);
    CPA_COMMIT();

    for (int ch = 0; ch < nch; ch++) {
        CPA_WAIT_ALL();
        __syncthreads();
        if (ch + 1 < nch) {
            load_stage(ch + 1, sb0 + (uint32_t)((ch + 1) & 1) * STAGE);
            CPA_COMMIT();
        }
        int ksubs = k16max - ch * 2;
        if (ksubs > 2) ksubs = 2;
        mma_stage32(sb0 + (uint32_t)(ch & 1) * STAGE, warp_m, warp_n, lane, acc, mfrags, ksubs);
    }

    epilogue_hl(Ch, Cl, m0, n0, warp_m, warp_n, lane, MGUARD ? Mvalid : (1 << 30), acc);
}

// ---------------------------------------------------------------------------
__global__ __launch_bounds__(256, 2) void tc_feat(
    const __half* __restrict__ Ah, const __half* __restrict__ Al,
    const __half* __restrict__ Bh, const __half* __restrict__ Bl,
    __half* __restrict__ Ch, __half* __restrict__ Cl, int K)
{
    extern __shared__ __align__(16) char smem[];
    uint32_t sb0 = cvta_s(smem);
    gemm_body<false>(Ah, Al, Bh, Bl, Ch, Cl, K, 1 << 30,
                     blockIdx.y * 128, blockIdx.x * 128, sb0);
}

__global__ __launch_bounds__(256, 2) void tc_adj(
    const __half* __restrict__ Amh, const __half* __restrict__ Aml,
    const __half* __restrict__ Sh,  const __half* __restrict__ Sl,
    __half* __restrict__ Hh, __half* __restrict__ Hl)
{
    extern __shared__ __align__(16) char smem[];
    uint32_t sb0 = cvta_s(smem);
    int z = blockIdx.z;
    gemm_body<true>(Amh + (size_t)z * NNODE * NNODE, Aml + (size_t)z * NNODE * NNODE,
                    Sh + (size_t)z * NNODE * HIDC,   Sl + (size_t)z * NNODE * HIDC,
                    Hh + (size_t)z * NNODE * HIDC,   Hl + (size_t)z * NNODE * HIDC,
                    NNODE, NNODE, blockIdx.y * 128, blockIdx.x * 128, sb0);
}

// ---------------------------------------------------------------------------
__global__ void mask_kernel(const float* __restrict__ raw) {
    int i = blockIdx.x * blockDim.x + threadIdx.x;
    if (i < NNODE * NNODE) {
        int r = i / NNODE, c = i % NNODE;
        float v = 0.5f * (raw[r * NNODE + c] + raw[c * NNODE + r]);
        if (r == c) v += 1.0f;
        d_mask[i] = v;
    }
}

__device__ __forceinline__ void split4_store(const float* v, __half* Hd, __half* Ld, size_t i4) {
    uint32_t h0, l0, h1, l1;
    split2(v[0], v[1], h0, l0);
    split2(v[2], v[3], h1, l1);
    ((uint2*)Hd)[i4] = make_uint2(h0, h1);
    ((uint2*)Ld)[i4] = make_uint2(l0, l1);
}

#define NA_Q ((size_t)BATCH * NNODE * NNODE / 4)
#define NF_Q ((size_t)BATCH * NNODE * INC / 4)
#define W0_Q (INC * HIDC / 4)
#define W1_Q (HIDC * HIDC / 4)
#define W2_Q (HIDC * HIDC / 4)
#define TOTAL_Q (NA_Q + NF_Q + W0_Q + W1_Q + W2_Q)

__global__ __launch_bounds__(256) void prep_kernel(
    const float* __restrict__ adj, const float* __restrict__ feat,
    const float* __restrict__ W0, const float* __restrict__ W1,
    const float* __restrict__ W2)
{
    size_t gid = (size_t)blockIdx.x * 256 + threadIdx.x;
    if (gid < NA_Q) {
        size_t base = gid * 4;
        int rem = (int)(base % (NNODE * NNODE));
        float4 x = *(const float4*)(adj + base);
        float4 m = *(const float4*)(d_mask + rem);
        float v[4];
        v[0] = m.x / (1.0f + __expf(-x.x));
        v[1] = m.y / (1.0f + __expf(-x.y));
        v[2] = m.z / (1.0f + __expf(-x.z));
        v[3] = m.w / (1.0f + __expf(-x.w));
        split4_store(v, d_Amh, d_Aml, gid);
    } else if (gid < NA_Q + NF_Q) {
        size_t i4 = gid - NA_Q;
        float4 x = *(const float4*)(feat + i4 * 4);
        float v[4] = {x.x, x.y, x.z, x.w};
        split4_store(v, d_Fh, d_Fl, i4);
    } else {
        size_t i = gid - NA_Q - NF_Q;
        const float* src; __half *Hd, *Ld; size_t i4;
        if (i < W0_Q)            { src = W0; Hd = d_W0h; Ld = d_W0l; i4 = i; }
        else if (i < W0_Q + W1_Q){ src = W1; Hd = d_W1h; Ld = d_W1l; i4 = i - W0_Q; }
        else if (i < W0_Q + W1_Q + W2_Q)
                                 { src = W2; Hd = d_W2h; Ld = d_W2l; i4 = i - W0_Q - W1_Q; }
        else return;
        float4 x = *(const float4*)(src + i4 * 4);
        float v[4] = {x.x, x.y, x.z, x.w};
        split4_store(v, Hd, Ld, i4);
    }
}

// ---------------------------------------------------------------------------
__global__ __launch_bounds__(256) void readout_kernel(
    const __half* __restrict__ Hh, const __half* __restrict__ Hl,
    const float* __restrict__ pw, const float* __restrict__ pb,
    float* __restrict__ out)
{
    int b = blockIdx.x;
    int c = threadIdx.x;
    const __half* Hbh = Hh + (size_t)b * NNODE * HIDC;
    const __half* Hbl = Hl + (size_t)b * NNODE * HIDC;

    float s = 0.0f;
    for (int n = 0; n < NNODE; n++)
        s += __half2float(Hbh[n * HIDC + c]) + __half2float(Hbl[n * HIDC + c]);
    s *= (1.0f / NNODE);

    __shared__ float r0[256], r1[256];
    r0[c] = s * pw[c * NVARS + 0];
    r1[c] = s * pw[c * NVARS + 1];
    __syncthreads();
    for (int off = 128; off > 0; off >>= 1) {
        if (c < off) { r0[c] += r0[c + off]; r1[c] += r1[c + off]; }
        __syncthreads();
    }
    if (c == 0) {
        out[b * NVARS + 0] = r0[0] + pb[0];
        out[b * NVARS + 1] = r1[0] + pb[1];
    }
}

// ---------------------------------------------------------------------------
extern "C" void kernel_launch(void* const* d_in, const int* in_sizes, int n_in,
                              void* d_out, int out_size)
{
    const float* adj      = (const float*)d_in[0];
    const float* features = (const float*)d_in[1];
    const float* raw      = (const float*)d_in[2];
    const float* W0       = (const float*)d_in[3];
    const float* W1       = (const float*)d_in[4];
    const float* W2       = (const float*)d_in[5];
    const float* pw       = (const float*)d_in[6];
    const float* pb       = (const float*)d_in[7];
    float* out = (float*)d_out;

    cudaFuncSetAttribute(tc_feat, cudaFuncAttributeMaxDynamicSharedMemorySize, SMEM_TOTAL);
    cudaFuncSetAttribute(tc_adj,  cudaFuncAttributeMaxDynamicSharedMemorySize, SMEM_TOTAL);

    __half *Amh, *Aml, *Fh, *Fl, *W0h, *W0l, *W1h, *W1l, *W2h, *W2l;
    __half *Sh, *Sl, *H1h, *H1l, *H2h, *H2l;
    cudaGetSymbolAddress((void**)&Amh, d_Amh); cudaGetSymbolAddress((void**)&Aml, d_Aml);
    cudaGetSymbolAddress((void**)&Fh, d_Fh);   cudaGetSymbolAddress((void**)&Fl, d_Fl);
    cudaGetSymbolAddress((void**)&W0h, d_W0h); cudaGetSymbolAddress((void**)&W0l, d_W0l);
    cudaGetSymbolAddress((void**)&W1h, d_W1h); cudaGetSymbolAddress((void**)&W1l, d_W1l);
    cudaGetSymbolAddress((void**)&W2h, d_W2h); cudaGetSymbolAddress((void**)&W2l, d_W2l);
    cudaGetSymbolAddress((void**)&Sh, d_Sh);   cudaGetSymbolAddress((void**)&Sl, d_Sl);
    cudaGetSymbolAddress((void**)&H1h, d_H1h); cudaGetSymbolAddress((void**)&H1l, d_H1l);
    cudaGetSymbolAddress((void**)&H2h, d_H2h); cudaGetSymbolAddress((void**)&H2l, d_H2l);

    mask_kernel<<<(NNODE * NNODE + 255) / 256, 256>>>(raw);
    prep_kernel<<<(unsigned)((TOTAL_Q + 255) / 256), 256>>>(adj, features, W0, W1, W2);

    dim3 gF(2, (BATCH * NNODE) / 128);   // (2, 800)
    dim3 gA(2, 2, BATCH);                // (ntile, mtile, batch)

    tc_feat<<<gF, 256, SMEM_TOTAL>>>(Fh, Fl, W0h, W0l, Sh, Sl, INC);
    tc_adj <<<gA, 256, SMEM_TOTAL>>>(Amh, Aml, Sh, Sl, H1h, H1l);

    tc_feat<<<gF, 256, SMEM_TOTAL>>>(H1h, H1l, W1h, W1l, Sh, Sl, HIDC);
    tc_adj <<<gA, 256, SMEM_TOTAL>>>(Amh, Aml, Sh, Sl, H2h, H2l);

    tc_feat<<<gF, 256, SMEM_TOTAL>>>(H2h, H2l, W2h, W2l, Sh, Sl, HIDC);
    tc_adj <<<gA, 256, SMEM_TOTAL>>>(Amh, Aml, Sh, Sl, H1h, H1l);

    readout_kernel<<<BATCH, 256>>>(H1h, H1l, pw, pb, out);
}